// round 4
// baseline (speedup 1.0000x reference)
#include <cuda_runtime.h>
#include <cuda_bf16.h>
#include <math.h>

// Problem constants
#define BB 32
#define TT 200
#define EE 256
#define HH 1024
#define VV 20000
#define G4 4096          // 4*H
#define RR (BB*TT)       // 6400 rows

// ---------------- scratch (static __device__, no allocs) ----------------
__device__ float g_pre0[RR * G4];          // precomputed layer0 input gates (+biases)
__device__ float g_partA[2 * BB * G4];     // layer0 W_hh k-split partials (2 slabs)
__device__ float g_partB[4 * BB * G4];     // layer1 k-split partials (4 slabs)
__device__ float g_h0[BB * HH];
__device__ float g_c0[BB * HH];
__device__ float g_h1[BB * HH];
__device__ float g_c1[BB * HH];
__device__ float g_outh[RR * HH];          // h1 per (b,t)

// ---------------- helpers ----------------
__device__ __forceinline__ unsigned tf32c(float f) {
    unsigned r;
    asm("cvt.rna.tf32.f32 %0, %1;" : "=r"(r) : "f"(f));
    return r;
}

__device__ __forceinline__ void mma8(float c[4], const unsigned a[4], const unsigned b[2]) {
    asm volatile(
        "mma.sync.aligned.m16n8k8.row.col.f32.tf32.tf32.f32 "
        "{%0,%1,%2,%3}, {%4,%5,%6,%7}, {%8,%9}, {%0,%1,%2,%3};\n"
        : "+f"(c[0]), "+f"(c[1]), "+f"(c[2]), "+f"(c[3])
        : "r"(a[0]), "r"(a[1]), "r"(a[2]), "r"(a[3]), "r"(b[0]), "r"(b[1]));
}

__device__ __forceinline__ float sigmoidf_(float x) {
    return 1.0f / (1.0f + expf(-x));
}

// ---------------- init states ----------------
__global__ void init_states() {
    int i = blockIdx.x * blockDim.x + threadIdx.x;
    if (i < BB * HH) {
        g_h0[i] = 0.f; g_c0[i] = 0.f; g_h1[i] = 0.f; g_c1[i] = 0.f;
    }
}

// ---------------- big GEMM (pre-gates & projection), tf32 mma ----------------
// mode 0: C = gather(emb, ids) @ W^T + bias1 + bias2  -> g_pre0   (M=6400,N=4096,K=256)
// mode 1: C = g_outh @ W^T + bias1  (masked rows skipped) -> out  (M=6400,N=20000,K=1024)
// BM=128, BN=128, 256 threads (8 warps as 2x4), warp tile 64x32.
__global__ void __launch_bounds__(256)
big_gemm(int mode, const int* __restrict__ ids, const float* __restrict__ emb,
         const float* __restrict__ W, const float* __restrict__ bias1,
         const float* __restrict__ bias2, const int* __restrict__ lengths,
         float* __restrict__ out, int N, int K)
{
    const int r0 = blockIdx.y * 128;
    const int c0 = blockIdx.x * 128;
    const int tid = threadIdx.x;
    const int lane = tid & 31, warp = tid >> 5;
    const int wm = warp >> 2, wn = warp & 3;
    const int lm = lane >> 2, lk = lane & 3;

    if (mode == 1) {
        int rr = r0 + (tid & 127);
        int t = rr % TT, b = rr / TT;
        int act = (t < lengths[b]) ? 1 : 0;
        if (!__syncthreads_or(act)) return;   // whole tile masked: copyfill handles it
    }

    // A row pointers (8 rows per thread) + store masks
    const float* ar[8];
    bool rmask[8];
    #pragma unroll
    for (int mt = 0; mt < 4; mt++) {
        int rl = wm * 64 + mt * 16 + lm;
        int gr0 = r0 + rl, gr1 = gr0 + 8;
        if (mode == 0) {
            ar[2*mt]   = emb + (size_t)ids[gr0] * K;
            ar[2*mt+1] = emb + (size_t)ids[gr1] * K;
            rmask[2*mt] = true; rmask[2*mt+1] = true;
        } else {
            ar[2*mt]   = g_outh + (size_t)gr0 * K;
            ar[2*mt+1] = g_outh + (size_t)gr1 * K;
            rmask[2*mt]   = (gr0 % TT) < lengths[gr0 / TT];
            rmask[2*mt+1] = (gr1 % TT) < lengths[gr1 / TT];
        }
    }
    // B row pointers (4 per thread), clamped for N overflow (stores guarded)
    const float* br[4];
    #pragma unroll
    for (int nt = 0; nt < 4; nt++) {
        int n = c0 + wn * 32 + nt * 8 + lm;
        br[nt] = W + (size_t)(n < N ? n : (N - 1)) * K;
    }

    float acc[4][4][4] = {};
    for (int k = 0; k < K; k += 8) {
        unsigned a[4][4], bf[4][2];
        #pragma unroll
        for (int mt = 0; mt < 4; mt++) {
            a[mt][0] = tf32c(ar[2*mt][k + lk]);
            a[mt][1] = tf32c(ar[2*mt+1][k + lk]);
            a[mt][2] = tf32c(ar[2*mt][k + 4 + lk]);
            a[mt][3] = tf32c(ar[2*mt+1][k + 4 + lk]);
        }
        #pragma unroll
        for (int nt = 0; nt < 4; nt++) {
            bf[nt][0] = tf32c(br[nt][k + lk]);
            bf[nt][1] = tf32c(br[nt][k + 4 + lk]);
        }
        #pragma unroll
        for (int mt = 0; mt < 4; mt++)
            #pragma unroll
            for (int nt = 0; nt < 4; nt++)
                mma8(acc[mt][nt], a[mt], bf[nt]);
    }

    float* outp = (mode == 0) ? g_pre0 : out;
    #pragma unroll
    for (int nt = 0; nt < 4; nt++) {
        int cc = c0 + wn * 32 + nt * 8 + (lk << 1);
        float bv0 = 0.f, bv1 = 0.f;
        bool v0 = cc < N, v1 = (cc + 1) < N;
        if (v0) { bv0 = bias1[cc];     if (bias2) bv0 += bias2[cc]; }
        if (v1) { bv1 = bias1[cc + 1]; if (bias2) bv1 += bias2[cc + 1]; }
        #pragma unroll
        for (int mt = 0; mt < 4; mt++) {
            int gr0 = r0 + wm * 64 + mt * 16 + lm;
            int gr1 = gr0 + 8;
            if (rmask[2*mt]) {
                if (v0) outp[(size_t)gr0 * N + cc]     = acc[mt][nt][0] + bv0;
                if (v1) outp[(size_t)gr0 * N + cc + 1] = acc[mt][nt][1] + bv1;
            }
            if (rmask[2*mt+1]) {
                if (v0) outp[(size_t)gr1 * N + cc]     = acc[mt][nt][2] + bv0;
                if (v1) outp[(size_t)gr1 * N + cc + 1] = acc[mt][nt][3] + bv1;
            }
        }
    }
}

// ---------------- recurrence step GEMM (fused gemm1(t) + gemm0(t+1)) ----------------
// 384 blocks x 128 threads. blocks [0,256): layer1 partials (64 coltiles x ksplit4, K=512);
// blocks [256,384): layer0 W_hh partials (64 coltiles x ksplit2, K=512).
// Each block: C[32 x 64] over K=512 via m16n8k8 tf32 mma (4 warps, 16 cols each).
__global__ void __launch_bounds__(128)
step_gemm(const float* __restrict__ Whh0, const float* __restrict__ Wih1,
          const float* __restrict__ Whh1, int doL0, int doL1)
{
    const int bx = blockIdx.x;
    const float* X; const float* W; int koff; float* outp; int n0col;
    if (bx < 256) {
        if (!doL1) return;
        int ct = bx & 63, ks = bx >> 6;
        if (ks < 2) { X = g_h0; W = Wih1; koff = ks * 512; }
        else        { X = g_h1; W = Whh1; koff = (ks - 2) * 512; }
        outp = g_partB + (size_t)ks * (BB * G4);
        n0col = ct * 64;
    } else {
        if (!doL0) return;
        int b2 = bx - 256;
        int ct = b2 & 63, ks = b2 >> 6;
        X = g_h0; W = Whh0; koff = ks * 512;
        outp = g_partA + (size_t)ks * (BB * G4);
        n0col = ct * 64;
    }

    const int lane = threadIdx.x & 31, warp = threadIdx.x >> 5;
    const int lm = lane >> 2, lk = lane & 3;
    const int n0 = n0col + warp * 16;

    const float* Xr  = X + lm * HH;                      // batch row lane/4
    const float* W0  = W + (size_t)(n0 + lm) * HH;       // ntile 0 row
    const float* W1  = W + (size_t)(n0 + 8 + lm) * HH;   // ntile 1 row

    float acc[2][2][4] = {};
    for (int kk = 0; kk < 512; kk += 8) {
        int k0 = koff + kk + lk;
        unsigned a[2][4], bf[2][2];
        #pragma unroll
        for (int mt = 0; mt < 2; mt++) {
            const float* xr = Xr + mt * 16 * HH;
            a[mt][0] = tf32c(xr[k0]);
            a[mt][1] = tf32c(xr[8 * HH + k0]);
            a[mt][2] = tf32c(xr[k0 + 4]);
            a[mt][3] = tf32c(xr[8 * HH + k0 + 4]);
        }
        bf[0][0] = tf32c(W0[k0]); bf[0][1] = tf32c(W0[k0 + 4]);
        bf[1][0] = tf32c(W1[k0]); bf[1][1] = tf32c(W1[k0 + 4]);
        mma8(acc[0][0], a[0], bf[0]); mma8(acc[0][1], a[0], bf[1]);
        mma8(acc[1][0], a[1], bf[0]); mma8(acc[1][1], a[1], bf[1]);
    }
    #pragma unroll
    for (int mt = 0; mt < 2; mt++) {
        int rA = mt * 16 + lm, rB = rA + 8;
        #pragma unroll
        for (int nt = 0; nt < 2; nt++) {
            int cc = n0 + nt * 8 + (lk << 1);
            outp[rA * G4 + cc]     = acc[mt][nt][0];
            outp[rA * G4 + cc + 1] = acc[mt][nt][1];
            outp[rB * G4 + cc]     = acc[mt][nt][2];
            outp[rB * G4 + cc + 1] = acc[mt][nt][3];
        }
    }
}

// ---------------- fused cell update: cell1(t) + cell0(t+1) ----------------
__global__ void __launch_bounds__(256)
cell_kernel(const float* __restrict__ b_ih1, const float* __restrict__ b_hh1,
            const int* __restrict__ lengths, int t, int doL0, int doL1)
{
    int idx = blockIdx.x * blockDim.x + threadIdx.x;   // 65536 threads
    int layer = idx >> 15;
    int e = idx & 32767;
    int b = e >> 10, j = e & 1023;

    if (layer == 0) {
        if (!doL0) return;
        int tn = t + 1;
        float s[4];
        #pragma unroll
        for (int g = 0; g < 4; g++) {
            int jj = j + g * HH;
            s[g] = g_partA[b * G4 + jj] + g_partA[BB * G4 + b * G4 + jj]
                 + g_pre0[(size_t)(b * TT + tn) * G4 + jj];
        }
        float ig = sigmoidf_(s[0]), fg = sigmoidf_(s[1]);
        float gg = tanhf(s[2]),     og = sigmoidf_(s[3]);
        float cold = g_c0[b * HH + j];
        float cn = fg * cold + ig * gg;
        float hn = og * tanhf(cn);
        bool m = tn < lengths[b];
        g_c0[b * HH + j] = m ? cn : cold;
        g_h0[b * HH + j] = m ? hn : g_h0[b * HH + j];
    } else {
        if (!doL1) return;
        float s[4];
        #pragma unroll
        for (int g = 0; g < 4; g++) {
            int jj = j + g * HH;
            float v = b_ih1[jj] + b_hh1[jj];
            #pragma unroll
            for (int ks = 0; ks < 4; ks++)
                v += g_partB[(size_t)ks * (BB * G4) + b * G4 + jj];
            s[g] = v;
        }
        float ig = sigmoidf_(s[0]), fg = sigmoidf_(s[1]);
        float gg = tanhf(s[2]),     og = sigmoidf_(s[3]);
        float cold = g_c1[b * HH + j];
        float cn = fg * cold + ig * gg;
        float hn = og * tanhf(cn);
        bool m = t < lengths[b];
        float cw = m ? cn : cold;
        float hw = m ? hn : g_h1[b * HH + j];
        g_c1[b * HH + j] = cw;
        g_h1[b * HH + j] = hw;
        g_outh[(size_t)(b * TT + t) * HH + j] = hw;
    }
}

// ---------------- fill masked rows: logits[b,t>=len] = logits[b,len-1] ----------------
__global__ void copyfill(const int* __restrict__ lengths, float* __restrict__ out)
{
    int t = blockIdx.x, b = blockIdx.y;
    int L = lengths[b];
    if (t < L) return;
    const float4* src = (const float4*)(out + ((size_t)b * TT + (L - 1)) * VV);
    float4* dst = (float4*)(out + ((size_t)b * TT + t) * VV);
    for (int i = threadIdx.x; i < VV / 4; i += blockDim.x) dst[i] = src[i];
}

// ---------------- launch ----------------
extern "C" void kernel_launch(void* const* d_in, const int* in_sizes, int n_in,
                              void* d_out, int out_size)
{
    const int*   ids     = (const int*)d_in[0];
    const int*   lengths = (const int*)d_in[1];
    const float* emb     = (const float*)d_in[2];
    const float* Wih0    = (const float*)d_in[3];
    const float* Whh0    = (const float*)d_in[4];
    const float* bih0    = (const float*)d_in[5];
    const float* bhh0    = (const float*)d_in[6];
    const float* Wih1    = (const float*)d_in[7];
    const float* Whh1    = (const float*)d_in[8];
    const float* bih1    = (const float*)d_in[9];
    const float* bhh1    = (const float*)d_in[10];
    const float* Wout    = (const float*)d_in[11];
    const float* bout    = (const float*)d_in[12];
    float* out = (float*)d_out;

    init_states<<<128, 256>>>();

    // Precompute layer0 input gates (+ both biases): M=6400, N=4096, K=256
    big_gemm<<<dim3(G4 / 128, RR / 128), 256>>>(0, ids, emb, Wih0, bih0, bhh0,
                                                nullptr, nullptr, G4, EE);

    // Prologue: gemm0 for step 0, then cell0(step 0)
    step_gemm<<<384, 128>>>(Whh0, Wih1, Whh1, 1, 0);
    cell_kernel<<<256, 256>>>(bih1, bhh1, lengths, -1, 1, 0);

    // Pipelined main loop: G(t) = gemm1(t) + gemm0(t+1); C(t) = cell1(t) + cell0(t+1)
    for (int t = 0; t < TT; t++) {
        int nxt = (t < TT - 1) ? 1 : 0;
        step_gemm<<<384, 128>>>(Whh0, Wih1, Whh1, nxt, 1);
        cell_kernel<<<256, 256>>>(bih1, bhh1, lengths, t, nxt, 1);
    }

    // Projection: logits = outh @ W_out^T + b_out (masked tiles skipped)
    big_gemm<<<dim3((VV + 127) / 128, RR / 128), 256>>>(1, nullptr, nullptr, Wout, bout,
                                                        nullptr, lengths, out, VV, HH);
    // Duplicate frozen rows
    copyfill<<<dim3(TT, BB), 256>>>(lengths, out);
}

// round 5
// speedup vs baseline: 1.0006x; 1.0006x over previous
#include <cuda_runtime.h>
#include <cuda_bf16.h>
#include <math.h>

// Problem constants
#define BB 32
#define TT 200
#define EE 256
#define HH 1024
#define VV 20000
#define G4 4096          // 4*H
#define RR (BB*TT)       // 6400 rows

// ---------------- scratch (static __device__, no allocs) ----------------
__device__ float g_pre0[RR * G4];          // precomputed layer0 input gates (+biases)
__device__ float g_partA[2 * BB * G4];     // layer0 W_hh k-split partials (2 slabs)
__device__ float g_partB[4 * BB * G4];     // layer1 k-split partials (4 slabs)
__device__ float g_h0[BB * HH];
__device__ float g_c0[BB * HH];
__device__ float g_h1[BB * HH];
__device__ float g_c1[BB * HH];
__device__ float g_outh[RR * HH];          // h1 per (b,t)

// ---------------- helpers ----------------
__device__ __forceinline__ unsigned tf32c(float f) {
    unsigned r;
    asm("cvt.rna.tf32.f32 %0, %1;" : "=r"(r) : "f"(f));
    return r;
}

__device__ __forceinline__ void mma8(float c[4], const unsigned a[4], const unsigned b[2]) {
    asm volatile(
        "mma.sync.aligned.m16n8k8.row.col.f32.tf32.tf32.f32 "
        "{%0,%1,%2,%3}, {%4,%5,%6,%7}, {%8,%9}, {%0,%1,%2,%3};\n"
        : "+f"(c[0]), "+f"(c[1]), "+f"(c[2]), "+f"(c[3])
        : "r"(a[0]), "r"(a[1]), "r"(a[2]), "r"(a[3]), "r"(b[0]), "r"(b[1]));
}

__device__ __forceinline__ float sigmoidf_(float x) {
    return 1.0f / (1.0f + expf(-x));
}

// ---------------- init states ----------------
__global__ void init_states() {
    int i = blockIdx.x * blockDim.x + threadIdx.x;
    if (i < BB * HH) {
        g_h0[i] = 0.f; g_c0[i] = 0.f; g_h1[i] = 0.f; g_c1[i] = 0.f;
    }
}

// ---------------- big GEMM (pre-gates & projection), tf32 mma ----------------
// mode 0: C = gather(emb, ids) @ W^T + bias1 + bias2  -> g_pre0   (M=6400,N=4096,K=256)
// mode 1: C = g_outh @ W^T + bias1  (masked rows skipped) -> out  (M=6400,N=20000,K=1024)
// BM=128, BN=128, 256 threads (8 warps as 2x4), warp tile 64x32.
__global__ void __launch_bounds__(256)
big_gemm(int mode, const int* __restrict__ ids, const float* __restrict__ emb,
         const float* __restrict__ W, const float* __restrict__ bias1,
         const float* __restrict__ bias2, const int* __restrict__ lengths,
         float* __restrict__ out, int N, int K)
{
    const int r0 = blockIdx.y * 128;
    const int c0 = blockIdx.x * 128;
    const int tid = threadIdx.x;
    const int lane = tid & 31, warp = tid >> 5;
    const int wm = warp >> 2, wn = warp & 3;
    const int lm = lane >> 2, lk = lane & 3;

    if (mode == 1) {
        int rr = r0 + (tid & 127);
        int t = rr % TT, b = rr / TT;
        int act = (t < lengths[b]) ? 1 : 0;
        if (!__syncthreads_or(act)) return;   // whole tile masked: copyfill handles it
    }

    // A row pointers (8 rows per thread) + store masks
    const float* ar[8];
    bool rmask[8];
    #pragma unroll
    for (int mt = 0; mt < 4; mt++) {
        int rl = wm * 64 + mt * 16 + lm;
        int gr0 = r0 + rl, gr1 = gr0 + 8;
        if (mode == 0) {
            ar[2*mt]   = emb + (size_t)ids[gr0] * K;
            ar[2*mt+1] = emb + (size_t)ids[gr1] * K;
            rmask[2*mt] = true; rmask[2*mt+1] = true;
        } else {
            ar[2*mt]   = g_outh + (size_t)gr0 * K;
            ar[2*mt+1] = g_outh + (size_t)gr1 * K;
            rmask[2*mt]   = (gr0 % TT) < lengths[gr0 / TT];
            rmask[2*mt+1] = (gr1 % TT) < lengths[gr1 / TT];
        }
    }
    // B row pointers (4 per thread), clamped for N overflow (stores guarded)
    const float* br[4];
    #pragma unroll
    for (int nt = 0; nt < 4; nt++) {
        int n = c0 + wn * 32 + nt * 8 + lm;
        br[nt] = W + (size_t)(n < N ? n : (N - 1)) * K;
    }

    float acc[4][4][4] = {};
    for (int k = 0; k < K; k += 8) {
        unsigned a[4][4], bf[4][2];
        #pragma unroll
        for (int mt = 0; mt < 4; mt++) {
            a[mt][0] = tf32c(ar[2*mt][k + lk]);
            a[mt][1] = tf32c(ar[2*mt+1][k + lk]);
            a[mt][2] = tf32c(ar[2*mt][k + 4 + lk]);
            a[mt][3] = tf32c(ar[2*mt+1][k + 4 + lk]);
        }
        #pragma unroll
        for (int nt = 0; nt < 4; nt++) {
            bf[nt][0] = tf32c(br[nt][k + lk]);
            bf[nt][1] = tf32c(br[nt][k + 4 + lk]);
        }
        #pragma unroll
        for (int mt = 0; mt < 4; mt++)
            #pragma unroll
            for (int nt = 0; nt < 4; nt++)
                mma8(acc[mt][nt], a[mt], bf[nt]);
    }

    float* outp = (mode == 0) ? g_pre0 : out;
    #pragma unroll
    for (int nt = 0; nt < 4; nt++) {
        int cc = c0 + wn * 32 + nt * 8 + (lk << 1);
        float bv0 = 0.f, bv1 = 0.f;
        bool v0 = cc < N, v1 = (cc + 1) < N;
        if (v0) { bv0 = bias1[cc];     if (bias2) bv0 += bias2[cc]; }
        if (v1) { bv1 = bias1[cc + 1]; if (bias2) bv1 += bias2[cc + 1]; }
        #pragma unroll
        for (int mt = 0; mt < 4; mt++) {
            int gr0 = r0 + wm * 64 + mt * 16 + lm;
            int gr1 = gr0 + 8;
            if (rmask[2*mt]) {
                if (v0) outp[(size_t)gr0 * N + cc]     = acc[mt][nt][0] + bv0;
                if (v1) outp[(size_t)gr0 * N + cc + 1] = acc[mt][nt][1] + bv1;
            }
            if (rmask[2*mt+1]) {
                if (v0) outp[(size_t)gr1 * N + cc]     = acc[mt][nt][2] + bv0;
                if (v1) outp[(size_t)gr1 * N + cc + 1] = acc[mt][nt][3] + bv1;
            }
        }
    }
}

// ---------------- recurrence step GEMM (fused gemm1(t) + gemm0(t+1)) ----------------
// 384 blocks x 128 threads. blocks [0,256): layer1 partials (64 coltiles x ksplit4, K=512);
// blocks [256,384): layer0 W_hh partials (64 coltiles x ksplit2, K=512).
// Each block: C[32 x 64] over K=512 via m16n8k8 tf32 mma (4 warps, 16 cols each).
__global__ void __launch_bounds__(128)
step_gemm(const float* __restrict__ Whh0, const float* __restrict__ Wih1,
          const float* __restrict__ Whh1, int doL0, int doL1)
{
    const int bx = blockIdx.x;
    const float* X; const float* W; int koff; float* outp; int n0col;
    if (bx < 256) {
        if (!doL1) return;
        int ct = bx & 63, ks = bx >> 6;
        if (ks < 2) { X = g_h0; W = Wih1; koff = ks * 512; }
        else        { X = g_h1; W = Whh1; koff = (ks - 2) * 512; }
        outp = g_partB + (size_t)ks * (BB * G4);
        n0col = ct * 64;
    } else {
        if (!doL0) return;
        int b2 = bx - 256;
        int ct = b2 & 63, ks = b2 >> 6;
        X = g_h0; W = Whh0; koff = ks * 512;
        outp = g_partA + (size_t)ks * (BB * G4);
        n0col = ct * 64;
    }

    const int lane = threadIdx.x & 31, warp = threadIdx.x >> 5;
    const int lm = lane >> 2, lk = lane & 3;
    const int n0 = n0col + warp * 16;

    const float* Xr  = X + lm * HH;                      // batch row lane/4
    const float* W0  = W + (size_t)(n0 + lm) * HH;       // ntile 0 row
    const float* W1  = W + (size_t)(n0 + 8 + lm) * HH;   // ntile 1 row

    float acc[2][2][4] = {};
    for (int kk = 0; kk < 512; kk += 8) {
        int k0 = koff + kk + lk;
        unsigned a[2][4], bf[2][2];
        #pragma unroll
        for (int mt = 0; mt < 2; mt++) {
            const float* xr = Xr + mt * 16 * HH;
            a[mt][0] = tf32c(xr[k0]);
            a[mt][1] = tf32c(xr[8 * HH + k0]);
            a[mt][2] = tf32c(xr[k0 + 4]);
            a[mt][3] = tf32c(xr[8 * HH + k0 + 4]);
        }
        bf[0][0] = tf32c(W0[k0]); bf[0][1] = tf32c(W0[k0 + 4]);
        bf[1][0] = tf32c(W1[k0]); bf[1][1] = tf32c(W1[k0 + 4]);
        mma8(acc[0][0], a[0], bf[0]); mma8(acc[0][1], a[0], bf[1]);
        mma8(acc[1][0], a[1], bf[0]); mma8(acc[1][1], a[1], bf[1]);
    }
    #pragma unroll
    for (int mt = 0; mt < 2; mt++) {
        int rA = mt * 16 + lm, rB = rA + 8;
        #pragma unroll
        for (int nt = 0; nt < 2; nt++) {
            int cc = n0 + nt * 8 + (lk << 1);
            outp[rA * G4 + cc]     = acc[mt][nt][0];
            outp[rA * G4 + cc + 1] = acc[mt][nt][1];
            outp[rB * G4 + cc]     = acc[mt][nt][2];
            outp[rB * G4 + cc + 1] = acc[mt][nt][3];
        }
    }
}

// ---------------- fused cell update: cell1(t) + cell0(t+1) ----------------
__global__ void __launch_bounds__(256)
cell_kernel(const float* __restrict__ b_ih1, const float* __restrict__ b_hh1,
            const int* __restrict__ lengths, int t, int doL0, int doL1)
{
    int idx = blockIdx.x * blockDim.x + threadIdx.x;   // 65536 threads
    int layer = idx >> 15;
    int e = idx & 32767;
    int b = e >> 10, j = e & 1023;

    if (layer == 0) {
        if (!doL0) return;
        int tn = t + 1;
        float s[4];
        #pragma unroll
        for (int g = 0; g < 4; g++) {
            int jj = j + g * HH;
            s[g] = g_partA[b * G4 + jj] + g_partA[BB * G4 + b * G4 + jj]
                 + g_pre0[(size_t)(b * TT + tn) * G4 + jj];
        }
        float ig = sigmoidf_(s[0]), fg = sigmoidf_(s[1]);
        float gg = tanhf(s[2]),     og = sigmoidf_(s[3]);
        float cold = g_c0[b * HH + j];
        float cn = fg * cold + ig * gg;
        float hn = og * tanhf(cn);
        bool m = tn < lengths[b];
        g_c0[b * HH + j] = m ? cn : cold;
        g_h0[b * HH + j] = m ? hn : g_h0[b * HH + j];
    } else {
        if (!doL1) return;
        float s[4];
        #pragma unroll
        for (int g = 0; g < 4; g++) {
            int jj = j + g * HH;
            float v = b_ih1[jj] + b_hh1[jj];
            #pragma unroll
            for (int ks = 0; ks < 4; ks++)
                v += g_partB[(size_t)ks * (BB * G4) + b * G4 + jj];
            s[g] = v;
        }
        float ig = sigmoidf_(s[0]), fg = sigmoidf_(s[1]);
        float gg = tanhf(s[2]),     og = sigmoidf_(s[3]);
        float cold = g_c1[b * HH + j];
        float cn = fg * cold + ig * gg;
        float hn = og * tanhf(cn);
        bool m = t < lengths[b];
        float cw = m ? cn : cold;
        float hw = m ? hn : g_h1[b * HH + j];
        g_c1[b * HH + j] = cw;
        g_h1[b * HH + j] = hw;
        g_outh[(size_t)(b * TT + t) * HH + j] = hw;
    }
}

// ---------------- fill masked rows: logits[b,t>=len] = logits[b,len-1] ----------------
__global__ void copyfill(const int* __restrict__ lengths, float* __restrict__ out)
{
    int t = blockIdx.x, b = blockIdx.y;
    int L = lengths[b];
    if (t < L) return;
    const float4* src = (const float4*)(out + ((size_t)b * TT + (L - 1)) * VV);
    float4* dst = (float4*)(out + ((size_t)b * TT + t) * VV);
    for (int i = threadIdx.x; i < VV / 4; i += blockDim.x) dst[i] = src[i];
}

// ---------------- launch ----------------
extern "C" void kernel_launch(void* const* d_in, const int* in_sizes, int n_in,
                              void* d_out, int out_size)
{
    const int*   ids     = (const int*)d_in[0];
    const int*   lengths = (const int*)d_in[1];
    const float* emb     = (const float*)d_in[2];
    const float* Wih0    = (const float*)d_in[3];
    const float* Whh0    = (const float*)d_in[4];
    const float* bih0    = (const float*)d_in[5];
    const float* bhh0    = (const float*)d_in[6];
    const float* Wih1    = (const float*)d_in[7];
    const float* Whh1    = (const float*)d_in[8];
    const float* bih1    = (const float*)d_in[9];
    const float* bhh1    = (const float*)d_in[10];
    const float* Wout    = (const float*)d_in[11];
    const float* bout    = (const float*)d_in[12];
    float* out = (float*)d_out;

    init_states<<<128, 256>>>();

    // Precompute layer0 input gates (+ both biases): M=6400, N=4096, K=256
    big_gemm<<<dim3(G4 / 128, RR / 128), 256>>>(0, ids, emb, Wih0, bih0, bhh0,
                                                nullptr, nullptr, G4, EE);

    // Prologue: gemm0 for step 0, then cell0(step 0)
    step_gemm<<<384, 128>>>(Whh0, Wih1, Whh1, 1, 0);
    cell_kernel<<<256, 256>>>(bih1, bhh1, lengths, -1, 1, 0);

    // Pipelined main loop: G(t) = gemm1(t) + gemm0(t+1); C(t) = cell1(t) + cell0(t+1)
    for (int t = 0; t < TT; t++) {
        int nxt = (t < TT - 1) ? 1 : 0;
        step_gemm<<<384, 128>>>(Whh0, Wih1, Whh1, nxt, 1);
        cell_kernel<<<256, 256>>>(bih1, bhh1, lengths, t, nxt, 1);
    }

    // Projection: logits = outh @ W_out^T + b_out (masked tiles skipped)
    big_gemm<<<dim3((VV + 127) / 128, RR / 128), 256>>>(1, nullptr, nullptr, Wout, bout,
                                                        nullptr, lengths, out, VV, HH);
    // Duplicate frozen rows
    copyfill<<<dim3(TT, BB), 256>>>(lengths, out);
}

// round 6
// speedup vs baseline: 1.4822x; 1.4813x over previous
#include <cuda_runtime.h>
#include <math.h>

// Problem constants
#define BB 32
#define TT 200
#define EE 256
#define HH 1024
#define VV 20000
#define G4 4096          // 4*H
#define RR (BB*TT)       // 6400 rows
#define NBLK 128         // persistent grid size (<=148 SMs -> co-resident)

// ---------------- scratch (static __device__, no allocs) ----------------
__device__ float g_pre0[(size_t)RR * G4];   // precomputed layer0 input gates (+biases)
__device__ float g_outh[(size_t)RR * HH];   // h1 per (b,t)
__device__ float g_h0[BB * HH];
__device__ float g_h1[BB * HH];
__device__ float g_gates0[BB * G4];         // layer0 Whh gates (step t+1)
__device__ float g_gates1[BB * G4];         // layer1 gates (step t)
__device__ unsigned g_cnt = 0;
__device__ volatile unsigned g_gen = 0;

// ---------------- helpers ----------------
__device__ __forceinline__ unsigned tf32c(float f) {
    unsigned r;
    asm("cvt.rna.tf32.f32 %0, %1;" : "=r"(r) : "f"(f));
    return r;
}

__device__ __forceinline__ void mma8(float c[4], const unsigned a[4], const unsigned b[2]) {
    asm volatile(
        "mma.sync.aligned.m16n8k8.row.col.f32.tf32.tf32.f32 "
        "{%0,%1,%2,%3}, {%4,%5,%6,%7}, {%8,%9}, {%0,%1,%2,%3};\n"
        : "+f"(c[0]), "+f"(c[1]), "+f"(c[2]), "+f"(c[3])
        : "r"(a[0]), "r"(a[1]), "r"(a[2]), "r"(a[3]), "r"(b[0]), "r"(b[1]));
}

__device__ __forceinline__ float sigmoidf_(float x) {
    return 1.0f / (1.0f + expf(-x));
}

// ---------------- grid barrier (all NBLK blocks) ----------------
__device__ __forceinline__ void gridbar() {
    __syncthreads();
    if (threadIdx.x == 0) {
        __threadfence();                       // release
        unsigned g = g_gen;
        if (atomicAdd(&g_cnt, 1u) == NBLK - 1u) {
            g_cnt = 0;
            __threadfence();
            g_gen = g + 1u;
        } else {
            while (g_gen == g) __nanosleep(40);
        }
    }
    __syncthreads();
    __threadfence();                           // acquire
}

// ---------------- per-block step GEMM (smem-staged, tf32 mma) ----------------
// Block computes C[32 x 64] = X @ W^T fully over K (2048 for L1: h0@Wih1 + h1@Whh1;
// 1024 for L0: h0@Whh0). 8 warps = 2 n-halves x 4 k-slices; Kc=64 chunks staged in smem
// with float4 coalesced loads + register prefetch. Cross-warp k-reduction in smem.
__device__ __forceinline__ void step_gemm_block(
    int isL1, int colbase,
    const float* __restrict__ Whh0, const float* __restrict__ Wih1,
    const float* __restrict__ Whh1, float* __restrict__ gatesOut,
    float* sm, int lane, int warp)
{
    const int lm = lane >> 2, lk = lane & 3;
    const int nhalf = warp & 1;        // which 32 of the 64 cols
    const int kslice = warp >> 1;      // 0..3, ksub=16 per chunk
    float* As = sm;                    // 32 x 68
    float* Bs = sm + 32 * 68;          // 64 x 68

    // staging indices (per thread): A: 2 float4, B: 4 float4 per chunk
    const int fA = threadIdx.x * 2;
    const int rA0 = fA >> 4,       qA0 = fA & 15;
    const int rA1 = (fA + 1) >> 4, qA1 = (fA + 1) & 15;
    const int fB = threadIdx.x * 4;
    int rB[4], qB[4];
    #pragma unroll
    for (int i = 0; i < 4; i++) { rB[i] = (fB + i) >> 4; qB[i] = (fB + i) & 15; }

    float acc[2][4][4];
    #pragma unroll
    for (int mt = 0; mt < 2; mt++)
        #pragma unroll
        for (int nt = 0; nt < 4; nt++)
            #pragma unroll
            for (int q = 0; q < 4; q++) acc[mt][nt][q] = 0.f;

    const int nch = isL1 ? 32 : 16;
    float4 pa0, pa1, pb[4];

    // prefetch chunk 0
    {
        const float* Ap = g_h0; const float* Bw = isL1 ? Wih1 : Whh0; int ko = 0;
        pa0 = __ldcg((const float4*)(Ap + rA0 * HH + ko + qA0 * 4));
        pa1 = __ldcg((const float4*)(Ap + rA1 * HH + ko + qA1 * 4));
        #pragma unroll
        for (int i = 0; i < 4; i++)
            pb[i] = __ldg((const float4*)(Bw + (size_t)(colbase + rB[i]) * HH + ko + qB[i] * 4));
    }

    for (int c = 0; c < nch; c++) {
        __syncthreads();
        *(float4*)&As[rA0 * 68 + qA0 * 4] = pa0;
        *(float4*)&As[rA1 * 68 + qA1 * 4] = pa1;
        #pragma unroll
        for (int i = 0; i < 4; i++)
            *(float4*)&Bs[rB[i] * 68 + qB[i] * 4] = pb[i];
        __syncthreads();

        if (c + 1 < nch) {
            int gk = (c + 1) << 6;
            const float* Ap; const float* Bw; int ko;
            if (isL1) {
                if (gk < 1024) { Ap = g_h0; Bw = Wih1; ko = gk; }
                else           { Ap = g_h1; Bw = Whh1; ko = gk - 1024; }
            } else { Ap = g_h0; Bw = Whh0; ko = gk; }
            pa0 = __ldcg((const float4*)(Ap + rA0 * HH + ko + qA0 * 4));
            pa1 = __ldcg((const float4*)(Ap + rA1 * HH + ko + qA1 * 4));
            #pragma unroll
            for (int i = 0; i < 4; i++)
                pb[i] = __ldg((const float4*)(Bw + (size_t)(colbase + rB[i]) * HH + ko + qB[i] * 4));
        }

        #pragma unroll
        for (int it = 0; it < 2; it++) {
            const int kk = kslice * 16 + it * 8;
            unsigned a[2][4], bq[4][2];
            #pragma unroll
            for (int mt = 0; mt < 2; mt++) {
                const float* Ar = &As[(mt * 16 + lm) * 68 + kk];
                a[mt][0] = tf32c(Ar[lk]);
                a[mt][1] = tf32c(Ar[8 * 68 + lk]);
                a[mt][2] = tf32c(Ar[lk + 4]);
                a[mt][3] = tf32c(Ar[8 * 68 + lk + 4]);
            }
            #pragma unroll
            for (int nt = 0; nt < 4; nt++) {
                const float* Br = &Bs[(nhalf * 32 + nt * 8 + lm) * 68 + kk];
                bq[nt][0] = tf32c(Br[lk]);
                bq[nt][1] = tf32c(Br[lk + 4]);
            }
            #pragma unroll
            for (int mt = 0; mt < 2; mt++)
                #pragma unroll
                for (int nt = 0; nt < 4; nt++)
                    mma8(acc[mt][nt], a[mt], bq[nt]);
        }
    }

    // cross-k-slice reduction via smem (reuses staging region)
    __syncthreads();
    float* p = sm;                     // 4 x 32 x 64 = 8192 floats
    #pragma unroll
    for (int mt = 0; mt < 2; mt++) {
        int r = mt * 16 + lm;
        #pragma unroll
        for (int nt = 0; nt < 4; nt++) {
            int cc = nhalf * 32 + nt * 8 + (lk << 1);
            p[kslice * 2048 + r * 64 + cc]           = acc[mt][nt][0];
            p[kslice * 2048 + r * 64 + cc + 1]       = acc[mt][nt][1];
            p[kslice * 2048 + (r + 8) * 64 + cc]     = acc[mt][nt][2];
            p[kslice * 2048 + (r + 8) * 64 + cc + 1] = acc[mt][nt][3];
        }
    }
    __syncthreads();
    {
        int o0 = threadIdx.x * 8;      // 256 threads x 8 = 2048 outputs
        float4 s0 = *(float4*)&p[o0];
        float4 s1 = *(float4*)&p[o0 + 4];
        #pragma unroll
        for (int ks = 1; ks < 4; ks++) {
            float4 t0 = *(float4*)&p[ks * 2048 + o0];
            float4 t1 = *(float4*)&p[ks * 2048 + o0 + 4];
            s0.x += t0.x; s0.y += t0.y; s0.z += t0.z; s0.w += t0.w;
            s1.x += t1.x; s1.y += t1.y; s1.z += t1.z; s1.w += t1.w;
        }
        int b = o0 >> 6, col = o0 & 63;
        float* gp = gatesOut + b * G4 + colbase + col;
        *(float4*)gp = s0;
        *(float4*)(gp + 4) = s1;
    }
    __syncthreads();   // protect smem before next use
}

// ---------------- persistent recurrence kernel ----------------
// blocks 0..63:  layer1 gates, cols [bid*64, +64), K=2048 (h0@Wih1 + h1@Whh1)
// blocks 64..127: layer0 gates (t+1), cols [(bid-64)*64, +64), K=1024 (h0@Whh0)
// Every thread also owns one (b,j) cell for layer0 AND layer1 (c in registers).
__global__ void __launch_bounds__(256)
persist_kernel(const float* __restrict__ Whh0, const float* __restrict__ Wih1,
               const float* __restrict__ Whh1, const float* __restrict__ bih1,
               const float* __restrict__ bhh1, const int* __restrict__ lengths)
{
    __shared__ float sm[8192];        // 32KB: staging (6528) / partials (8192)
    const int bid = blockIdx.x, tid = threadIdx.x;
    const int lane = tid & 31, warp = tid >> 5;
    const int isL1 = bid < 64;
    const int colbase = (isL1 ? bid : bid - 64) * 64;

    const int gtid = bid * 256 + tid;            // 0..32767
    const int b = gtid >> 10, j = gtid & 1023;
    const int len = lengths[b];
    const float bs0 = bih1[j]        + bhh1[j];
    const float bs1 = bih1[j + 1024] + bhh1[j + 1024];
    const float bs2 = bih1[j + 2048] + bhh1[j + 2048];
    const float bs3 = bih1[j + 3072] + bhh1[j + 3072];

    float c0r, c1r = 0.f, h1r = 0.f;
    g_h1[gtid] = 0.f;
    // prologue: cell0(t=0): h_prev = 0 -> gates = pre0[b,0]; mask always true (len>=1)
    {
        const float* pg = g_pre0 + (size_t)(b * TT) * G4 + j;
        float ig = sigmoidf_(pg[0]);
        float fg = sigmoidf_(pg[1024]); (void)fg;
        float gg = tanhf(pg[2048]);
        float og = sigmoidf_(pg[3072]);
        c0r = ig * gg;
        g_h0[gtid] = og * tanhf(c0r);
    }
    gridbar();

    for (int t = 0; t < TT; t++) {
        // ---- phase A: GEMMs ----
        if (isL1) {
            step_gemm_block(1, colbase, Whh0, Wih1, Whh1, g_gates1, sm, lane, warp);
        } else if (t < TT - 1) {
            step_gemm_block(0, colbase, Whh0, Wih1, Whh1, g_gates0, sm, lane, warp);
        }
        gridbar();

        // ---- phase B: cells ----
        {   // cell1(t)
            const float* gp = g_gates1 + b * G4 + j;
            float si = __ldcg(gp)        + bs0;
            float sf = __ldcg(gp + 1024) + bs1;
            float sg = __ldcg(gp + 2048) + bs2;
            float so = __ldcg(gp + 3072) + bs3;
            float ig = sigmoidf_(si), fg = sigmoidf_(sf);
            float gg = tanhf(sg),     og = sigmoidf_(so);
            float cn = fg * c1r + ig * gg;
            float hn = og * tanhf(cn);
            if (t < len) { c1r = cn; h1r = hn; g_h1[gtid] = h1r; }
            g_outh[(size_t)(b * TT + t) * HH + j] = h1r;
        }
        if (t < TT - 1) {   // cell0(t+1)
            const float* gp = g_gates0 + b * G4 + j;
            const float* pp = g_pre0 + (size_t)(b * TT + t + 1) * G4 + j;
            float si = __ldcg(gp)        + pp[0];
            float sf = __ldcg(gp + 1024) + pp[1024];
            float sg = __ldcg(gp + 2048) + pp[2048];
            float so = __ldcg(gp + 3072) + pp[3072];
            float ig = sigmoidf_(si), fg = sigmoidf_(sf);
            float gg = tanhf(sg),     og = sigmoidf_(so);
            float cn = fg * c0r + ig * gg;
            if (t + 1 < len) { c0r = cn; g_h0[gtid] = og * tanhf(cn); }
        }
        gridbar();
    }
}

// ---------------- tiled big GEMM (pre-gates & projection), smem-staged ----------------
// mode 0: C = gather(emb, ids) @ W^T + bias1 + bias2 -> g_pre0  (M=6400,N=4096,K=256)
// mode 1: C = g_outh @ W^T + bias1 -> out  (M=6400,N=20000,K=1024), fully-masked
//         row tiles skipped (copyfill handles them).
// BM=BN=128, Kc=32, 256 threads (8 warps as 2x4), warp tile 64x32, register prefetch.
__global__ void __launch_bounds__(256)
tile_gemm(int mode, const int* __restrict__ ids, const float* __restrict__ emb,
          const float* __restrict__ W, const float* __restrict__ bias1,
          const float* __restrict__ bias2, const int* __restrict__ lengths,
          float* __restrict__ outp, int N, int K)
{
    __shared__ float As[128 * 36];
    __shared__ float Bs[128 * 36];
    const int r0 = blockIdx.y * 128, c0 = blockIdx.x * 128;
    const int tid = threadIdx.x;
    const int lane = tid & 31, warp = tid >> 5;
    const int wm = warp >> 2, wn = warp & 3;
    const int lm = lane >> 2, lk = lane & 3;

    if (mode == 1) {
        int rr = r0 + (tid & 127);
        int act = ((rr % TT) < lengths[rr / TT]) ? 1 : 0;
        if (!__syncthreads_or(act)) return;
    }

    // staging: each thread stages 16 consecutive floats (4 float4) of row tid/2
    const int srow = tid >> 1;
    const int qb = (tid & 1) * 4;     // float4 index base within the 8 per row
    const float* Asrc;
    if (mode == 0) Asrc = emb + (size_t)ids[r0 + srow] * K;
    else           Asrc = g_outh + (size_t)(r0 + srow) * K;
    int nr = c0 + srow; if (nr > N - 1) nr = N - 1;
    const float* Bsrc = W + (size_t)nr * K;

    float acc[4][4][4];
    #pragma unroll
    for (int mt = 0; mt < 4; mt++)
        #pragma unroll
        for (int nt = 0; nt < 4; nt++)
            #pragma unroll
            for (int q = 0; q < 4; q++) acc[mt][nt][q] = 0.f;

    const int nch = K >> 5;
    float4 av[4], bv[4];
    #pragma unroll
    for (int i = 0; i < 4; i++) {
        av[i] = __ldg((const float4*)(Asrc + (qb + i) * 4));
        bv[i] = __ldg((const float4*)(Bsrc + (qb + i) * 4));
    }

    for (int c = 0; c < nch; c++) {
        __syncthreads();
        #pragma unroll
        for (int i = 0; i < 4; i++) {
            *(float4*)&As[srow * 36 + (qb + i) * 4] = av[i];
            *(float4*)&Bs[srow * 36 + (qb + i) * 4] = bv[i];
        }
        __syncthreads();
        if (c + 1 < nch) {
            int k0 = (c + 1) << 5;
            #pragma unroll
            for (int i = 0; i < 4; i++) {
                av[i] = __ldg((const float4*)(Asrc + k0 + (qb + i) * 4));
                bv[i] = __ldg((const float4*)(Bsrc + k0 + (qb + i) * 4));
            }
        }
        #pragma unroll
        for (int it = 0; it < 4; it++) {
            const int kk = it * 8;
            unsigned a[4][4], bq[4][2];
            #pragma unroll
            for (int mt = 0; mt < 4; mt++) {
                const float* Ar = &As[(wm * 64 + mt * 16 + lm) * 36 + kk];
                a[mt][0] = tf32c(Ar[lk]);
                a[mt][1] = tf32c(Ar[8 * 36 + lk]);
                a[mt][2] = tf32c(Ar[lk + 4]);
                a[mt][3] = tf32c(Ar[8 * 36 + lk + 4]);
            }
            #pragma unroll
            for (int nt = 0; nt < 4; nt++) {
                const float* Br = &Bs[(wn * 32 + nt * 8 + lm) * 36 + kk];
                bq[nt][0] = tf32c(Br[lk]);
                bq[nt][1] = tf32c(Br[lk + 4]);
            }
            #pragma unroll
            for (int mt = 0; mt < 4; mt++)
                #pragma unroll
                for (int nt = 0; nt < 4; nt++)
                    mma8(acc[mt][nt], a[mt], bq[nt]);
        }
    }

    float* dst = (mode == 0) ? g_pre0 : outp;
    #pragma unroll
    for (int nt = 0; nt < 4; nt++) {
        int cc = c0 + wn * 32 + nt * 8 + (lk << 1);
        bool v0 = cc < N, v1 = (cc + 1) < N;
        float bv0 = 0.f, bv1 = 0.f;
        if (v0) { bv0 = bias1[cc];     if (bias2) bv0 += bias2[cc]; }
        if (v1) { bv1 = bias1[cc + 1]; if (bias2) bv1 += bias2[cc + 1]; }
        #pragma unroll
        for (int mt = 0; mt < 4; mt++) {
            int gr0 = r0 + wm * 64 + mt * 16 + lm;
            int gr1 = gr0 + 8;
            if (v0) dst[(size_t)gr0 * N + cc]     = acc[mt][nt][0] + bv0;
            if (v1) dst[(size_t)gr0 * N + cc + 1] = acc[mt][nt][1] + bv1;
            if (v0) dst[(size_t)gr1 * N + cc]     = acc[mt][nt][2] + bv0;
            if (v1) dst[(size_t)gr1 * N + cc + 1] = acc[mt][nt][3] + bv1;
        }
    }
}

// ---------------- fill masked rows: logits[b, t>=len] = logits[b, len-1] ----------------
__global__ void copyfill(const int* __restrict__ lengths, float* __restrict__ out)
{
    int t = blockIdx.x, b = blockIdx.y;
    int L = lengths[b];
    if (t < L) return;
    const float4* src = (const float4*)(out + ((size_t)b * TT + (L - 1)) * VV);
    float4* dst = (float4*)(out + ((size_t)b * TT + t) * VV);
    for (int i = threadIdx.x; i < VV / 4; i += blockDim.x) dst[i] = src[i];
}

// ---------------- launch ----------------
extern "C" void kernel_launch(void* const* d_in, const int* in_sizes, int n_in,
                              void* d_out, int out_size)
{
    const int*   ids     = (const int*)d_in[0];
    const int*   lengths = (const int*)d_in[1];
    const float* emb     = (const float*)d_in[2];
    const float* Wih0    = (const float*)d_in[3];
    const float* Whh0    = (const float*)d_in[4];
    const float* bih0    = (const float*)d_in[5];
    const float* bhh0    = (const float*)d_in[6];
    const float* Wih1    = (const float*)d_in[7];
    const float* Whh1    = (const float*)d_in[8];
    const float* bih1    = (const float*)d_in[9];
    const float* bhh1    = (const float*)d_in[10];
    const float* Wout    = (const float*)d_in[11];
    const float* bout    = (const float*)d_in[12];
    float* out = (float*)d_out;

    // 1) precompute layer0 input gates (+ both biases): M=6400, N=4096, K=256
    tile_gemm<<<dim3(G4 / 128, RR / 128), 256>>>(0, ids, emb, Wih0, bih0, bhh0,
                                                 nullptr, nullptr, G4, EE);

    // 2) full recurrence in one persistent kernel (grid barriers between phases)
    persist_kernel<<<NBLK, 256>>>(Whh0, Wih1, Whh1, bih1, bhh1, lengths);

    // 3) projection: logits = outh @ W_out^T + b_out (fully-masked tiles skipped)
    tile_gemm<<<dim3((VV + 127) / 128, RR / 128), 256>>>(1, nullptr, nullptr, Wout, bout,
                                                         nullptr, lengths, out, VV, HH);
    // 4) duplicate frozen rows
    copyfill<<<dim3(TT, BB), 256>>>(lengths, out);
}

// round 9
// speedup vs baseline: 1.7370x; 1.1719x over previous
#include <cuda_runtime.h>
#include <cuda_fp16.h>
#include <math.h>

// Problem constants
#define BB 32
#define TT 200
#define EE 256
#define HH 1024
#define VV 20000
#define G4 4096          // 4*H
#define RR (BB*TT)       // 6400 rows
#define NBLK 128         // persistent grid size (<=148 SMs -> co-resident)

// ---------------- scratch (static __device__, no allocs) ----------------
__device__ float  g_pre0[(size_t)RR * G4];   // precomputed layer0 input gates (+biases)
__device__ __half g_outhh[(size_t)RR * HH];  // h1 per (b,t), fp16 (proj A operand)
__device__ float  g_h0[BB * HH];
__device__ float  g_h1[BB * HH];
__device__ float  g_gates0[BB * G4];         // layer0 Whh gates (step t+1)
__device__ float  g_gates1[BB * G4];         // layer1 gates (step t)
__device__ float  rWhh0[(size_t)G4 * HH];    // tf32-pre-rounded fp32 weights
__device__ float  rWih1[(size_t)G4 * HH];
__device__ float  rWhh1[(size_t)G4 * HH];
__device__ __half hWih0[(size_t)G4 * EE];    // fp16 weights (big GEMMs)
__device__ __half hWout[(size_t)VV * HH];
__device__ float  g_b0[G4];                  // bih0+bhh0 combined
__device__ unsigned g_cnt = 0;
__device__ volatile unsigned g_gen = 0;

// ---------------- helpers ----------------
__device__ __forceinline__ unsigned tf32c(float f) {
    unsigned r;
    asm("cvt.rna.tf32.f32 %0, %1;" : "=r"(r) : "f"(f));
    return r;
}

__device__ __forceinline__ void mma8(float c[4], const unsigned a[4], const unsigned b[2]) {
    asm volatile(
        "mma.sync.aligned.m16n8k8.row.col.f32.tf32.tf32.f32 "
        "{%0,%1,%2,%3}, {%4,%5,%6,%7}, {%8,%9}, {%0,%1,%2,%3};\n"
        : "+f"(c[0]), "+f"(c[1]), "+f"(c[2]), "+f"(c[3])
        : "r"(a[0]), "r"(a[1]), "r"(a[2]), "r"(a[3]), "r"(b[0]), "r"(b[1]));
}

__device__ __forceinline__ void mma16(float c[4], const unsigned a[4], const unsigned b[2]) {
    asm volatile(
        "mma.sync.aligned.m16n8k16.row.col.f32.f16.f16.f32 "
        "{%0,%1,%2,%3}, {%4,%5,%6,%7}, {%8,%9}, {%0,%1,%2,%3};\n"
        : "+f"(c[0]), "+f"(c[1]), "+f"(c[2]), "+f"(c[3])
        : "r"(a[0]), "r"(a[1]), "r"(a[2]), "r"(a[3]), "r"(b[0]), "r"(b[1]));
}

__device__ __forceinline__ float sigmoidf_(float x) {
    return 1.0f / (1.0f + expf(-x));
}

// ---------------- grid barrier (all NBLK blocks) ----------------
__device__ __forceinline__ void gridbar() {
    __syncthreads();
    if (threadIdx.x == 0) {
        __threadfence();                       // release
        unsigned g = g_gen;
        if (atomicAdd(&g_cnt, 1u) == NBLK - 1u) {
            g_cnt = 0;
            __threadfence();
            g_gen = g + 1u;
        } else {
            while (g_gen == g) __nanosleep(40);
        }
    }
    __syncthreads();
    __threadfence();                           // acquire
}

// ---------------- conversion kernels ----------------
// tf32-round fp32 weights in place format (fp32 bits with low mantissa zeroed by RNA)
__global__ void round_w(float* dst, const float* __restrict__ src) {
    size_t i = ((size_t)blockIdx.x * 256 + threadIdx.x) * 4;
    float4 f = *(const float4*)(src + i);
    f.x = __uint_as_float(tf32c(f.x));
    f.y = __uint_as_float(tf32c(f.y));
    f.z = __uint_as_float(tf32c(f.z));
    f.w = __uint_as_float(tf32c(f.w));
    *(float4*)(dst + i) = f;
}

__global__ void conv_h16(__half* dst, const float* __restrict__ src) {
    size_t i = ((size_t)blockIdx.x * 256 + threadIdx.x) * 4;
    float4 f = *(const float4*)(src + i);
    *(__half2*)(dst + i)     = __floats2half2_rn(f.x, f.y);
    *(__half2*)(dst + i + 2) = __floats2half2_rn(f.z, f.w);
}

__global__ void conv_b0(const float* bi0, const float* bh0) {
    int i = blockIdx.x * blockDim.x + threadIdx.x;
    if (i < G4) g_b0[i] = bi0[i] + bh0[i];
}

// ---------------- pre-GEMM: g_pre0 = gather(emb,ids) @ Wih0^T + b0 (fp16 mma) --------
// M=6400, N=4096, K=256. BM=BN=128, Kc=32.
__global__ void __launch_bounds__(256)
pre_gemm(const int* __restrict__ ids, const float* __restrict__ emb,
         const int* __restrict__ lengths)
{
    __shared__ __half As[128 * 40];
    __shared__ __half Bs[128 * 40];
    const int r0 = blockIdx.y * 128, c0 = blockIdx.x * 128;
    const int tid = threadIdx.x, lane = tid & 31, warp = tid >> 5;
    const int wm = warp >> 2, wn = warp & 3, lm = lane >> 2, lk = lane & 3;

    const int srow = tid >> 1, soff = (tid & 1) * 16;
    const float*  Asrc = emb + (size_t)ids[r0 + srow] * EE;
    const __half* Bsrc = hWih0 + (size_t)(c0 + srow) * EE;

    float acc[4][4][4];
    #pragma unroll
    for (int mt = 0; mt < 4; mt++)
        #pragma unroll
        for (int nt = 0; nt < 4; nt++)
            #pragma unroll
            for (int q = 0; q < 4; q++) acc[mt][nt][q] = 0.f;

    float4 af[4]; uint4 bv0, bv1;
    #pragma unroll
    for (int i = 0; i < 4; i++) af[i] = *(const float4*)(Asrc + soff + i * 4);
    bv0 = *(const uint4*)(Bsrc + soff);
    bv1 = *(const uint4*)(Bsrc + soff + 8);

    const int nch = EE / 32;   // 8
    for (int c = 0; c < nch; c++) {
        __syncthreads();
        {
            __half2* ad = (__half2*)&As[srow * 40 + soff];
            ad[0] = __floats2half2_rn(af[0].x, af[0].y);
            ad[1] = __floats2half2_rn(af[0].z, af[0].w);
            ad[2] = __floats2half2_rn(af[1].x, af[1].y);
            ad[3] = __floats2half2_rn(af[1].z, af[1].w);
            ad[4] = __floats2half2_rn(af[2].x, af[2].y);
            ad[5] = __floats2half2_rn(af[2].z, af[2].w);
            ad[6] = __floats2half2_rn(af[3].x, af[3].y);
            ad[7] = __floats2half2_rn(af[3].z, af[3].w);
            *(uint4*)&Bs[srow * 40 + soff]     = bv0;
            *(uint4*)&Bs[srow * 40 + soff + 8] = bv1;
        }
        __syncthreads();
        if (c + 1 < nch) {
            int k0 = (c + 1) * 32;
            #pragma unroll
            for (int i = 0; i < 4; i++) af[i] = *(const float4*)(Asrc + k0 + soff + i * 4);
            bv0 = *(const uint4*)(Bsrc + k0 + soff);
            bv1 = *(const uint4*)(Bsrc + k0 + soff + 8);
        }
        #pragma unroll
        for (int it = 0; it < 2; it++) {
            const int kw = it * 16 + 2 * lk;
            unsigned a[4][4], b[4][2];
            #pragma unroll
            for (int mt = 0; mt < 4; mt++) {
                const __half* Ar = &As[(wm * 64 + mt * 16 + lm) * 40 + kw];
                a[mt][0] = *(const unsigned*)Ar;
                a[mt][1] = *(const unsigned*)(Ar + 8 * 40);
                a[mt][2] = *(const unsigned*)(Ar + 8);
                a[mt][3] = *(const unsigned*)(Ar + 8 * 40 + 8);
            }
            #pragma unroll
            for (int nt = 0; nt < 4; nt++) {
                const __half* Br = &Bs[(wn * 32 + nt * 8 + lm) * 40 + kw];
                b[nt][0] = *(const unsigned*)Br;
                b[nt][1] = *(const unsigned*)(Br + 8);
            }
            #pragma unroll
            for (int mt = 0; mt < 4; mt++)
                #pragma unroll
                for (int nt = 0; nt < 4; nt++)
                    mma16(acc[mt][nt], a[mt], b[nt]);
        }
    }

    #pragma unroll
    for (int nt = 0; nt < 4; nt++) {
        int cc = c0 + wn * 32 + nt * 8 + 2 * lk;
        float b0 = g_b0[cc], b1 = g_b0[cc + 1];
        #pragma unroll
        for (int mt = 0; mt < 4; mt++) {
            int gr0 = r0 + wm * 64 + mt * 16 + lm, gr1 = gr0 + 8;
            g_pre0[(size_t)gr0 * G4 + cc]     = acc[mt][nt][0] + b0;
            g_pre0[(size_t)gr0 * G4 + cc + 1] = acc[mt][nt][1] + b1;
            g_pre0[(size_t)gr1 * G4 + cc]     = acc[mt][nt][2] + b0;
            g_pre0[(size_t)gr1 * G4 + cc + 1] = acc[mt][nt][3] + b1;
        }
    }
}

// ---------------- per-block step GEMM (smem-staged, tf32 mma) -- R6 structure -------
// Block computes C[32 x 64] = X @ W^T fully over K (2048 for L1: h0@Wih1 + h1@Whh1;
// 1024 for L0: h0@Whh0). 8 warps = 2 n-halves x 4 k-slices; Kc=64 chunks staged in smem.
// B operands are tf32-pre-rounded fp32 (no cvt); A (h) is cvt'd at staging time.
__device__ __forceinline__ void step_gemm_block(
    int isL1, int colbase, float* __restrict__ gatesOut,
    float* sm, int lane, int warp)
{
    const int lm = lane >> 2, lk = lane & 3;
    const int nhalf = warp & 1;        // which 32 of the 64 cols
    const int kslice = warp >> 1;      // 0..3, ksub=16 per chunk
    float* As = sm;                    // 32 x 68
    float* Bs = sm + 32 * 68;          // 64 x 68

    // staging indices (per thread): A: 2 float4, B: 4 float4 per chunk
    const int fA = threadIdx.x * 2;
    const int rA0 = fA >> 4,       qA0 = fA & 15;
    const int rA1 = (fA + 1) >> 4, qA1 = (fA + 1) & 15;
    const int fB = threadIdx.x * 4;
    int rB[4], qB[4];
    #pragma unroll
    for (int i = 0; i < 4; i++) { rB[i] = (fB + i) >> 4; qB[i] = (fB + i) & 15; }

    float acc[2][4][4];
    #pragma unroll
    for (int mt = 0; mt < 2; mt++)
        #pragma unroll
        for (int nt = 0; nt < 4; nt++)
            #pragma unroll
            for (int q = 0; q < 4; q++) acc[mt][nt][q] = 0.f;

    const int nch = isL1 ? 32 : 16;
    float4 pa0, pa1, pb[4];

    // prefetch chunk 0
    {
        const float* Ap = g_h0; const float* Bw = isL1 ? rWih1 : rWhh0; int ko = 0;
        pa0 = __ldcg((const float4*)(Ap + rA0 * HH + ko + qA0 * 4));
        pa1 = __ldcg((const float4*)(Ap + rA1 * HH + ko + qA1 * 4));
        #pragma unroll
        for (int i = 0; i < 4; i++)
            pb[i] = __ldg((const float4*)(Bw + (size_t)(colbase + rB[i]) * HH + ko + qB[i] * 4));
    }

    for (int c = 0; c < nch; c++) {
        __syncthreads();
        {   // A staged with tf32 rounding applied once here
            float4 r0, r1;
            r0.x = __uint_as_float(tf32c(pa0.x)); r0.y = __uint_as_float(tf32c(pa0.y));
            r0.z = __uint_as_float(tf32c(pa0.z)); r0.w = __uint_as_float(tf32c(pa0.w));
            r1.x = __uint_as_float(tf32c(pa1.x)); r1.y = __uint_as_float(tf32c(pa1.y));
            r1.z = __uint_as_float(tf32c(pa1.z)); r1.w = __uint_as_float(tf32c(pa1.w));
            *(float4*)&As[rA0 * 68 + qA0 * 4] = r0;
            *(float4*)&As[rA1 * 68 + qA1 * 4] = r1;
        }
        #pragma unroll
        for (int i = 0; i < 4; i++)
            *(float4*)&Bs[rB[i] * 68 + qB[i] * 4] = pb[i];
        __syncthreads();

        if (c + 1 < nch) {
            int gk = (c + 1) << 6;
            const float* Ap; const float* Bw; int ko;
            if (isL1) {
                if (gk < 1024) { Ap = g_h0; Bw = rWih1; ko = gk; }
                else           { Ap = g_h1; Bw = rWhh1; ko = gk - 1024; }
            } else { Ap = g_h0; Bw = rWhh0; ko = gk; }
            pa0 = __ldcg((const float4*)(Ap + rA0 * HH + ko + qA0 * 4));
            pa1 = __ldcg((const float4*)(Ap + rA1 * HH + ko + qA1 * 4));
            #pragma unroll
            for (int i = 0; i < 4; i++)
                pb[i] = __ldg((const float4*)(Bw + (size_t)(colbase + rB[i]) * HH + ko + qB[i] * 4));
        }

        #pragma unroll
        for (int it = 0; it < 2; it++) {
            const int kk = kslice * 16 + it * 8;
            unsigned a[2][4], bq[4][2];
            #pragma unroll
            for (int mt = 0; mt < 2; mt++) {
                const float* Ar = &As[(mt * 16 + lm) * 68 + kk];
                a[mt][0] = __float_as_uint(Ar[lk]);
                a[mt][1] = __float_as_uint(Ar[8 * 68 + lk]);
                a[mt][2] = __float_as_uint(Ar[lk + 4]);
                a[mt][3] = __float_as_uint(Ar[8 * 68 + lk + 4]);
            }
            #pragma unroll
            for (int nt = 0; nt < 4; nt++) {
                const float* Br = &Bs[(nhalf * 32 + nt * 8 + lm) * 68 + kk];
                bq[nt][0] = __float_as_uint(Br[lk]);
                bq[nt][1] = __float_as_uint(Br[lk + 4]);
            }
            #pragma unroll
            for (int mt = 0; mt < 2; mt++)
                #pragma unroll
                for (int nt = 0; nt < 4; nt++)
                    mma8(acc[mt][nt], a[mt], bq[nt]);
        }
    }

    // cross-k-slice reduction via smem (reuses staging region)
    __syncthreads();
    float* p = sm;                     // 4 x 32 x 64 = 8192 floats
    #pragma unroll
    for (int mt = 0; mt < 2; mt++) {
        int r = mt * 16 + lm;
        #pragma unroll
        for (int nt = 0; nt < 4; nt++) {
            int cc = nhalf * 32 + nt * 8 + (lk << 1);
            p[kslice * 2048 + r * 64 + cc]           = acc[mt][nt][0];
            p[kslice * 2048 + r * 64 + cc + 1]       = acc[mt][nt][1];
            p[kslice * 2048 + (r + 8) * 64 + cc]     = acc[mt][nt][2];
            p[kslice * 2048 + (r + 8) * 64 + cc + 1] = acc[mt][nt][3];
        }
    }
    __syncthreads();
    {
        int o0 = threadIdx.x * 8;      // 256 threads x 8 = 2048 outputs
        float4 s0 = *(float4*)&p[o0];
        float4 s1 = *(float4*)&p[o0 + 4];
        #pragma unroll
        for (int ks = 1; ks < 4; ks++) {
            float4 t0 = *(float4*)&p[ks * 2048 + o0];
            float4 t1 = *(float4*)&p[ks * 2048 + o0 + 4];
            s0.x += t0.x; s0.y += t0.y; s0.z += t0.z; s0.w += t0.w;
            s1.x += t1.x; s1.y += t1.y; s1.z += t1.z; s1.w += t1.w;
        }
        int b = o0 >> 6, col = o0 & 63;
        float* gp = gatesOut + b * G4 + colbase + col;
        *(float4*)gp = s0;
        *(float4*)(gp + 4) = s1;
    }
    __syncthreads();   // protect smem before next use
}

// ---------------- persistent recurrence kernel (R6 structure) ----------------
// blocks 0..63:  layer1 gates, cols [bid*64, +64), K=2048 (h0@Wih1 + h1@Whh1)
// blocks 64..127: layer0 gates (t+1), cols [(bid-64)*64, +64), K=1024 (h0@Whh0)
// Every thread also owns one (b,j) cell for layer0 AND layer1 (c in registers).
__global__ void __launch_bounds__(256)
persist_kernel(const float* __restrict__ bih1, const float* __restrict__ bhh1,
               const int* __restrict__ lengths)
{
    __shared__ float sm[8192];        // 32KB: staging (6528) / partials (8192)
    const int bid = blockIdx.x, tid = threadIdx.x;
    const int lane = tid & 31, warp = tid >> 5;
    const int isL1 = bid < 64;
    const int colbase = (isL1 ? bid : bid - 64) * 64;

    const int gtid = bid * 256 + tid;            // 0..32767
    const int b = gtid >> 10, j = gtid & 1023;
    const int len = lengths[b];
    const float bs0 = bih1[j]        + bhh1[j];
    const float bs1 = bih1[j + 1024] + bhh1[j + 1024];
    const float bs2 = bih1[j + 2048] + bhh1[j + 2048];
    const float bs3 = bih1[j + 3072] + bhh1[j + 3072];

    float c0r, c1r = 0.f, h1r = 0.f;
    g_h1[gtid] = 0.f;
    // prologue: cell0(t=0): h_prev = 0 -> gates = pre0[b,0]; mask always true (len>=1)
    {
        const float* pg = g_pre0 + (size_t)(b * TT) * G4 + j;
        float ig = sigmoidf_(pg[0]);
        float gg = tanhf(pg[2048]);
        float og = sigmoidf_(pg[3072]);
        c0r = ig * gg;
        g_h0[gtid] = og * tanhf(c0r);
    }
    gridbar();

    for (int t = 0; t < TT; t++) {
        // ---- phase A: GEMMs ----
        if (isL1) {
            step_gemm_block(1, colbase, g_gates1, sm, lane, warp);
        } else if (t < TT - 1) {
            step_gemm_block(0, colbase, g_gates0, sm, lane, warp);
        }
        gridbar();

        // ---- phase B: cells ----
        {   // cell1(t)
            const float* gp = g_gates1 + b * G4 + j;
            float si = __ldcg(gp)        + bs0;
            float sf = __ldcg(gp + 1024) + bs1;
            float sg = __ldcg(gp + 2048) + bs2;
            float so = __ldcg(gp + 3072) + bs3;
            float ig = sigmoidf_(si), fg = sigmoidf_(sf);
            float gg = tanhf(sg),     og = sigmoidf_(so);
            float cn = fg * c1r + ig * gg;
            float hn = og * tanhf(cn);
            if (t < len) { c1r = cn; h1r = hn; g_h1[gtid] = h1r; }
            g_outhh[(size_t)(b * TT + t) * HH + j] = __float2half_rn(h1r);
        }
        if (t < TT - 1) {   // cell0(t+1)
            const float* gp = g_gates0 + b * G4 + j;
            const float* pp = g_pre0 + (size_t)(b * TT + t + 1) * G4 + j;
            float si = __ldcg(gp)        + pp[0];
            float sf = __ldcg(gp + 1024) + pp[1024];
            float sg = __ldcg(gp + 2048) + pp[2048];
            float so = __ldcg(gp + 3072) + pp[3072];
            float ig = sigmoidf_(si), fg = sigmoidf_(sf);
            float gg = tanhf(sg),     og = sigmoidf_(so);
            float cn = fg * c0r + ig * gg;
            if (t + 1 < len) { c0r = cn; g_h0[gtid] = og * tanhf(cn); }
        }
        gridbar();
    }
}

// ---------------- projection: logits = outh(fp16) @ Wout(fp16)^T + bout -------------
// M=6400, N=20000, K=1024. BM=BN=128, Kc=32, fully-masked row tiles skipped.
__global__ void __launch_bounds__(256)
proj_gemm(const float* __restrict__ bout, const int* __restrict__ lengths,
          float* __restrict__ out)
{
    __shared__ __half As[128 * 40];
    __shared__ __half Bs[128 * 40];
    const int r0 = blockIdx.y * 128, c0 = blockIdx.x * 128;
    const int tid = threadIdx.x, lane = tid & 31, warp = tid >> 5;
    const int wm = warp >> 2, wn = warp & 3, lm = lane >> 2, lk = lane & 3;

    {
        int rr = r0 + (tid & 127);
        int act = ((rr % TT) < lengths[rr / TT]) ? 1 : 0;
        if (!__syncthreads_or(act)) return;
    }

    const int srow = tid >> 1, soff = (tid & 1) * 16;
    const __half* Asrc = g_outhh + (size_t)(r0 + srow) * HH;
    int nr = c0 + srow; if (nr > VV - 1) nr = VV - 1;
    const __half* Bsrc = hWout + (size_t)nr * HH;

    float acc[4][4][4];
    #pragma unroll
    for (int mt = 0; mt < 4; mt++)
        #pragma unroll
        for (int nt = 0; nt < 4; nt++)
            #pragma unroll
            for (int q = 0; q < 4; q++) acc[mt][nt][q] = 0.f;

    uint4 av0, av1, bv0, bv1;
    av0 = *(const uint4*)(Asrc + soff);     av1 = *(const uint4*)(Asrc + soff + 8);
    bv0 = *(const uint4*)(Bsrc + soff);     bv1 = *(const uint4*)(Bsrc + soff + 8);

    for (int c = 0; c < 32; c++) {
        __syncthreads();
        *(uint4*)&As[srow * 40 + soff]     = av0;
        *(uint4*)&As[srow * 40 + soff + 8] = av1;
        *(uint4*)&Bs[srow * 40 + soff]     = bv0;
        *(uint4*)&Bs[srow * 40 + soff + 8] = bv1;
        __syncthreads();
        if (c + 1 < 32) {
            int k0 = (c + 1) * 32;
            av0 = *(const uint4*)(Asrc + k0 + soff); av1 = *(const uint4*)(Asrc + k0 + soff + 8);
            bv0 = *(const uint4*)(Bsrc + k0 + soff); bv1 = *(const uint4*)(Bsrc + k0 + soff + 8);
        }
        #pragma unroll
        for (int it = 0; it < 2; it++) {
            const int kw = it * 16 + 2 * lk;
            unsigned a[4][4], b[4][2];
            #pragma unroll
            for (int mt = 0; mt < 4; mt++) {
                const __half* Ar = &As[(wm * 64 + mt * 16 + lm) * 40 + kw];
                a[mt][0] = *(const unsigned*)Ar;
                a[mt][1] = *(const unsigned*)(Ar + 8 * 40);
                a[mt][2] = *(const unsigned*)(Ar + 8);
                a[mt][3] = *(const unsigned*)(Ar + 8 * 40 + 8);
            }
            #pragma unroll
            for (int nt = 0; nt < 4; nt++) {
                const __half* Br = &Bs[(wn * 32 + nt * 8 + lm) * 40 + kw];
                b[nt][0] = *(const unsigned*)Br;
                b[nt][1] = *(const unsigned*)(Br + 8);
            }
            #pragma unroll
            for (int mt = 0; mt < 4; mt++)
                #pragma unroll
                for (int nt = 0; nt < 4; nt++)
                    mma16(acc[mt][nt], a[mt], b[nt]);
        }
    }

    bool rmask[8];
    #pragma unroll
    for (int mt = 0; mt < 4; mt++) {
        int gr0 = r0 + wm * 64 + mt * 16 + lm, gr1 = gr0 + 8;
        rmask[2 * mt]     = (gr0 % TT) < lengths[gr0 / TT];
        rmask[2 * mt + 1] = (gr1 % TT) < lengths[gr1 / TT];
    }
    #pragma unroll
    for (int nt = 0; nt < 4; nt++) {
        int cc = c0 + wn * 32 + nt * 8 + 2 * lk;
        bool v0 = cc < VV, v1 = (cc + 1) < VV;
        float b0 = v0 ? bout[cc] : 0.f, b1 = v1 ? bout[cc + 1] : 0.f;
        #pragma unroll
        for (int mt = 0; mt < 4; mt++) {
            int gr0 = r0 + wm * 64 + mt * 16 + lm, gr1 = gr0 + 8;
            if (rmask[2 * mt]) {
                if (v0) out[(size_t)gr0 * VV + cc]     = acc[mt][nt][0] + b0;
                if (v1) out[(size_t)gr0 * VV + cc + 1] = acc[mt][nt][1] + b1;
            }
            if (rmask[2 * mt + 1]) {
                if (v0) out[(size_t)gr1 * VV + cc]     = acc[mt][nt][2] + b0;
                if (v1) out[(size_t)gr1 * VV + cc + 1] = acc[mt][nt][3] + b1;
            }
        }
    }
}

// ---------------- fill masked rows: logits[b, t>=len] = logits[b, len-1] ----------------
__global__ void copyfill(const int* __restrict__ lengths, float* __restrict__ out)
{
    int t = blockIdx.x, b = blockIdx.y;
    int L = lengths[b];
    if (t < L) return;
    const float4* src = (const float4*)(out + ((size_t)b * TT + (L - 1)) * VV);
    float4* dst = (float4*)(out + ((size_t)b * TT + t) * VV);
    for (int i = threadIdx.x; i < VV / 4; i += blockDim.x) dst[i] = src[i];
}

// ---------------- launch ----------------
extern "C" void kernel_launch(void* const* d_in, const int* in_sizes, int n_in,
                              void* d_out, int out_size)
{
    const int*   ids     = (const int*)d_in[0];
    const int*   lengths = (const int*)d_in[1];
    const float* emb     = (const float*)d_in[2];
    const float* Wih0    = (const float*)d_in[3];
    const float* Whh0    = (const float*)d_in[4];
    const float* bih0    = (const float*)d_in[5];
    const float* bhh0    = (const float*)d_in[6];
    const float* Wih1    = (const float*)d_in[7];
    const float* Whh1    = (const float*)d_in[8];
    const float* bih1    = (const float*)d_in[9];
    const float* bhh1    = (const float*)d_in[10];
    const float* Wout    = (const float*)d_in[11];
    const float* bout    = (const float*)d_in[12];
    float* out = (float*)d_out;

    // 0) weight prep: tf32-round recurrence weights; fp16 for big GEMMs; bias combine
    float* rw0; float* rw1; float* rw2; __half* hw0; __half* hwo;
    cudaGetSymbolAddress((void**)&rw0, rWhh0);
    cudaGetSymbolAddress((void**)&rw1, rWih1);
    cudaGetSymbolAddress((void**)&rw2, rWhh1);
    cudaGetSymbolAddress((void**)&hw0, hWih0);
    cudaGetSymbolAddress((void**)&hwo, hWout);
    round_w<<<4096, 256>>>(rw0, Whh0);          // 4096*1024 floats
    round_w<<<4096, 256>>>(rw1, Wih1);
    round_w<<<4096, 256>>>(rw2, Whh1);
    conv_h16<<<1024, 256>>>(hw0, Wih0);         // 4096*256
    conv_h16<<<20000, 256>>>(hwo, Wout);        // 20000*1024
    conv_b0<<<16, 256>>>(bih0, bhh0);

    // 1) precompute layer0 input gates (+biases): M=6400, N=4096, K=256 (fp16 mma)
    pre_gemm<<<dim3(G4 / 128, RR / 128), 256>>>(ids, emb, lengths);

    // 2) full recurrence in one persistent kernel (R6-proven two-phase, tf32 mma)
    persist_kernel<<<NBLK, 256>>>(bih1, bhh1, lengths);

    // 3) projection (fp16 operands, fp32 accumulate/output)
    proj_gemm<<<dim3((VV + 127) / 128, RR / 128), 256>>>(bout, lengths, out);

    // 4) duplicate frozen rows
    copyfill<<<dim3(TT, BB), 256>>>(lengths, out);
}

// round 10
// speedup vs baseline: 2.6253x; 1.5114x over previous
#include <cuda_runtime.h>
#include <cuda_fp16.h>
#include <math.h>

// Problem constants
#define BB 32
#define TT 200
#define EE 256
#define HH 1024
#define VV 20000
#define G4 4096          // 4*H
#define RR (BB*TT)       // 6400 rows
#define NBLK 128         // persistent grid size (<=148 SMs -> co-resident)

// ---------------- scratch (static __device__, no allocs) ----------------
__device__ float  g_pre0[(size_t)RR * G4];   // precomputed layer0 input gates (+biases)
__device__ __half g_outhh[(size_t)RR * HH];  // h1 per (b,t), fp16 (proj A operand)
__device__ __half g_hh0[BB * HH];            // h0 state, fp16
__device__ __half g_hh1[BB * HH];            // h1 state, fp16
__device__ float  g_gates0[BB * G4];         // layer0 Whh gates (step t+1)
__device__ float  g_gates1[BB * G4];         // layer1 gates (step t)
__device__ __half hWhh0[(size_t)G4 * HH];    // fp16 weights
__device__ __half hWih1[(size_t)G4 * HH];
__device__ __half hWhh1[(size_t)G4 * HH];
__device__ __half hWih0[(size_t)G4 * EE];
__device__ __half hWout[(size_t)VV * HH];
__device__ float  g_b0[G4];                  // bih0+bhh0 combined
__device__ unsigned g_cnt = 0;
__device__ volatile unsigned g_gen = 0;

// ---------------- helpers ----------------
__device__ __forceinline__ void mma16(float c[4], const unsigned a[4], const unsigned b[2]) {
    asm volatile(
        "mma.sync.aligned.m16n8k16.row.col.f32.f16.f16.f32 "
        "{%0,%1,%2,%3}, {%4,%5,%6,%7}, {%8,%9}, {%0,%1,%2,%3};\n"
        : "+f"(c[0]), "+f"(c[1]), "+f"(c[2]), "+f"(c[3])
        : "r"(a[0]), "r"(a[1]), "r"(a[2]), "r"(a[3]), "r"(b[0]), "r"(b[1]));
}

__device__ __forceinline__ float sigmoidf_(float x) {
    return 1.0f / (1.0f + expf(-x));
}

// ---------------- grid barrier (all NBLK blocks) ----------------
__device__ __forceinline__ void gridbar() {
    __syncthreads();
    if (threadIdx.x == 0) {
        __threadfence();                       // release
        unsigned g = g_gen;
        if (atomicAdd(&g_cnt, 1u) == NBLK - 1u) {
            g_cnt = 0;
            __threadfence();
            g_gen = g + 1u;
        } else {
            while (g_gen == g) __nanosleep(30);
        }
    }
    __syncthreads();
    __threadfence();                           // acquire
}

// ---------------- conversion kernels ----------------
__global__ void conv_h16(__half* dst, const float* __restrict__ src) {
    size_t i = ((size_t)blockIdx.x * 256 + threadIdx.x) * 4;
    float4 f = *(const float4*)(src + i);
    *(__half2*)(dst + i)     = __floats2half2_rn(f.x, f.y);
    *(__half2*)(dst + i + 2) = __floats2half2_rn(f.z, f.w);
}

__global__ void conv_b0(const float* bi0, const float* bh0) {
    int i = blockIdx.x * blockDim.x + threadIdx.x;
    if (i < G4) g_b0[i] = bi0[i] + bh0[i];
}

// ---------------- pre-GEMM: g_pre0 = gather(emb,ids) @ Wih0^T + b0 (fp16 mma) --------
// M=6400, N=4096, K=256. BM=BN=128, Kc=32.  (R9-proven)
__global__ void __launch_bounds__(256)
pre_gemm(const int* __restrict__ ids, const float* __restrict__ emb,
         const int* __restrict__ lengths)
{
    __shared__ __half As[128 * 40];
    __shared__ __half Bs[128 * 40];
    const int r0 = blockIdx.y * 128, c0 = blockIdx.x * 128;
    const int tid = threadIdx.x, lane = tid & 31, warp = tid >> 5;
    const int wm = warp >> 2, wn = warp & 3, lm = lane >> 2, lk = lane & 3;

    const int srow = tid >> 1, soff = (tid & 1) * 16;
    const float*  Asrc = emb + (size_t)ids[r0 + srow] * EE;
    const __half* Bsrc = hWih0 + (size_t)(c0 + srow) * EE;

    float acc[4][4][4];
    #pragma unroll
    for (int mt = 0; mt < 4; mt++)
        #pragma unroll
        for (int nt = 0; nt < 4; nt++)
            #pragma unroll
            for (int q = 0; q < 4; q++) acc[mt][nt][q] = 0.f;

    float4 af[4]; uint4 bv0, bv1;
    #pragma unroll
    for (int i = 0; i < 4; i++) af[i] = *(const float4*)(Asrc + soff + i * 4);
    bv0 = *(const uint4*)(Bsrc + soff);
    bv1 = *(const uint4*)(Bsrc + soff + 8);

    const int nch = EE / 32;   // 8
    for (int c = 0; c < nch; c++) {
        __syncthreads();
        {
            __half2* ad = (__half2*)&As[srow * 40 + soff];
            ad[0] = __floats2half2_rn(af[0].x, af[0].y);
            ad[1] = __floats2half2_rn(af[0].z, af[0].w);
            ad[2] = __floats2half2_rn(af[1].x, af[1].y);
            ad[3] = __floats2half2_rn(af[1].z, af[1].w);
            ad[4] = __floats2half2_rn(af[2].x, af[2].y);
            ad[5] = __floats2half2_rn(af[2].z, af[2].w);
            ad[6] = __floats2half2_rn(af[3].x, af[3].y);
            ad[7] = __floats2half2_rn(af[3].z, af[3].w);
            *(uint4*)&Bs[srow * 40 + soff]     = bv0;
            *(uint4*)&Bs[srow * 40 + soff + 8] = bv1;
        }
        __syncthreads();
        if (c + 1 < nch) {
            int k0 = (c + 1) * 32;
            #pragma unroll
            for (int i = 0; i < 4; i++) af[i] = *(const float4*)(Asrc + k0 + soff + i * 4);
            bv0 = *(const uint4*)(Bsrc + k0 + soff);
            bv1 = *(const uint4*)(Bsrc + k0 + soff + 8);
        }
        #pragma unroll
        for (int it = 0; it < 2; it++) {
            const int kw = it * 16 + 2 * lk;
            unsigned a[4][4], b[4][2];
            #pragma unroll
            for (int mt = 0; mt < 4; mt++) {
                const __half* Ar = &As[(wm * 64 + mt * 16 + lm) * 40 + kw];
                a[mt][0] = *(const unsigned*)Ar;
                a[mt][1] = *(const unsigned*)(Ar + 8 * 40);
                a[mt][2] = *(const unsigned*)(Ar + 8);
                a[mt][3] = *(const unsigned*)(Ar + 8 * 40 + 8);
            }
            #pragma unroll
            for (int nt = 0; nt < 4; nt++) {
                const __half* Br = &Bs[(wn * 32 + nt * 8 + lm) * 40 + kw];
                b[nt][0] = *(const unsigned*)Br;
                b[nt][1] = *(const unsigned*)(Br + 8);
            }
            #pragma unroll
            for (int mt = 0; mt < 4; mt++)
                #pragma unroll
                for (int nt = 0; nt < 4; nt++)
                    mma16(acc[mt][nt], a[mt], b[nt]);
        }
    }

    #pragma unroll
    for (int nt = 0; nt < 4; nt++) {
        int cc = c0 + wn * 32 + nt * 8 + 2 * lk;
        float b0 = g_b0[cc], b1 = g_b0[cc + 1];
        #pragma unroll
        for (int mt = 0; mt < 4; mt++) {
            int gr0 = r0 + wm * 64 + mt * 16 + lm, gr1 = gr0 + 8;
            g_pre0[(size_t)gr0 * G4 + cc]     = acc[mt][nt][0] + b0;
            g_pre0[(size_t)gr0 * G4 + cc + 1] = acc[mt][nt][1] + b1;
            g_pre0[(size_t)gr1 * G4 + cc]     = acc[mt][nt][2] + b0;
            g_pre0[(size_t)gr1 * G4 + cc + 1] = acc[mt][nt][3] + b1;
        }
    }
}

// ---------------- per-block step GEMM (fp16 smem-staged, mma16) ----------------
// Block computes C[32 x 64] = X @ W^T over K (2048 for L1: h0@Wih1 + h1@Whh1;
// 1024 for L0: h0@Whh0). 8 warps = 2 n-halves x 4 k-slices; Kc=128 halves/chunk.
// smem stride 136 halves (conflict-free fragment reads: bank = 4*lm+lk).
__device__ __forceinline__ void step_gemm_block(
    int isL1, int colbase, float* __restrict__ gatesOut,
    float* sm, int lane, int warp)
{
    const int lm = lane >> 2, lk = lane & 3;
    const int nhalf = warp & 1;        // which 32 of the 64 cols
    const int ksl = warp >> 1;         // 0..3, 32 k per chunk
    __half* As = (__half*)sm;                 // 32 x 136 halves
    __half* Bs = (__half*)sm + 32 * 136;      // 64 x 136 halves

    // staging (per thread): A: 2 uint4 (8 halves each), B: 4 uint4. 16 uint4/row.
    const int fA = threadIdx.x * 2;
    const int rA0 = fA >> 4,       qA0 = fA & 15;
    const int rA1 = (fA + 1) >> 4, qA1 = (fA + 1) & 15;
    const int fB = threadIdx.x * 4;
    int rB[4], qB[4];
    #pragma unroll
    for (int i = 0; i < 4; i++) { rB[i] = (fB + i) >> 4; qB[i] = (fB + i) & 15; }

    float acc[2][4][4];
    #pragma unroll
    for (int mt = 0; mt < 2; mt++)
        #pragma unroll
        for (int nt = 0; nt < 4; nt++)
            #pragma unroll
            for (int q = 0; q < 4; q++) acc[mt][nt][q] = 0.f;

    const int nch = isL1 ? 16 : 8;     // Kc=128 halves
    uint4 pa0, pa1, pb[4];

    // prefetch chunk 0
    {
        const __half* Ap = g_hh0;
        const __half* Bw = isL1 ? hWih1 : hWhh0;
        pa0 = __ldcg((const uint4*)(Ap + rA0 * HH + qA0 * 8));
        pa1 = __ldcg((const uint4*)(Ap + rA1 * HH + qA1 * 8));
        #pragma unroll
        for (int i = 0; i < 4; i++)
            pb[i] = __ldg((const uint4*)(Bw + (size_t)(colbase + rB[i]) * HH + qB[i] * 8));
    }

    for (int c = 0; c < nch; c++) {
        __syncthreads();
        *(uint4*)&As[rA0 * 136 + qA0 * 8] = pa0;
        *(uint4*)&As[rA1 * 136 + qA1 * 8] = pa1;
        #pragma unroll
        for (int i = 0; i < 4; i++)
            *(uint4*)&Bs[rB[i] * 136 + qB[i] * 8] = pb[i];
        __syncthreads();

        if (c + 1 < nch) {
            int cc = c + 1;
            const __half* Ap; const __half* Bw; int ko;
            if (isL1) {
                if (cc < 8) { Ap = g_hh0; Bw = hWih1; ko = cc * 128; }
                else        { Ap = g_hh1; Bw = hWhh1; ko = (cc - 8) * 128; }
            } else { Ap = g_hh0; Bw = hWhh0; ko = cc * 128; }
            pa0 = __ldcg((const uint4*)(Ap + rA0 * HH + ko + qA0 * 8));
            pa1 = __ldcg((const uint4*)(Ap + rA1 * HH + ko + qA1 * 8));
            #pragma unroll
            for (int i = 0; i < 4; i++)
                pb[i] = __ldg((const uint4*)(Bw + (size_t)(colbase + rB[i]) * HH + ko + qB[i] * 8));
        }

        #pragma unroll
        for (int it = 0; it < 2; it++) {
            const int kw = ksl * 32 + it * 16 + 2 * lk;
            unsigned a[2][4], bq[4][2];
            #pragma unroll
            for (int mt = 0; mt < 2; mt++) {
                const __half* Ar = &As[(mt * 16 + lm) * 136 + kw];
                a[mt][0] = *(const unsigned*)Ar;
                a[mt][1] = *(const unsigned*)(Ar + 8 * 136);
                a[mt][2] = *(const unsigned*)(Ar + 8);
                a[mt][3] = *(const unsigned*)(Ar + 8 * 136 + 8);
            }
            #pragma unroll
            for (int nt = 0; nt < 4; nt++) {
                const __half* Br = &Bs[(nhalf * 32 + nt * 8 + lm) * 136 + kw];
                bq[nt][0] = *(const unsigned*)Br;
                bq[nt][1] = *(const unsigned*)(Br + 8);
            }
            #pragma unroll
            for (int mt = 0; mt < 2; mt++)
                #pragma unroll
                for (int nt = 0; nt < 4; nt++)
                    mma16(acc[mt][nt], a[mt], bq[nt]);
        }
    }

    // cross-k-slice reduction via smem (reuses staging region)
    __syncthreads();
    float* p = sm;                     // 4 x 32 x 64 = 8192 floats
    #pragma unroll
    for (int mt = 0; mt < 2; mt++) {
        int r = mt * 16 + lm;
        #pragma unroll
        for (int nt = 0; nt < 4; nt++) {
            int cc = nhalf * 32 + nt * 8 + (lk << 1);
            p[ksl * 2048 + r * 64 + cc]           = acc[mt][nt][0];
            p[ksl * 2048 + r * 64 + cc + 1]       = acc[mt][nt][1];
            p[ksl * 2048 + (r + 8) * 64 + cc]     = acc[mt][nt][2];
            p[ksl * 2048 + (r + 8) * 64 + cc + 1] = acc[mt][nt][3];
        }
    }
    __syncthreads();
    {
        int o0 = threadIdx.x * 8;      // 256 threads x 8 = 2048 outputs
        float4 s0 = *(float4*)&p[o0];
        float4 s1 = *(float4*)&p[o0 + 4];
        #pragma unroll
        for (int ks = 1; ks < 4; ks++) {
            float4 t0 = *(float4*)&p[ks * 2048 + o0];
            float4 t1 = *(float4*)&p[ks * 2048 + o0 + 4];
            s0.x += t0.x; s0.y += t0.y; s0.z += t0.z; s0.w += t0.w;
            s1.x += t1.x; s1.y += t1.y; s1.z += t1.z; s1.w += t1.w;
        }
        int b = o0 >> 6, col = o0 & 63;
        float* gp = gatesOut + b * G4 + colbase + col;
        *(float4*)gp = s0;
        *(float4*)(gp + 4) = s1;
    }
    __syncthreads();   // protect smem before next use
}

// ---------------- persistent recurrence kernel (R6/R9 two-phase structure) ----------
// blocks 0..63:  layer1 gates, cols [bid*64, +64), K=2048 (h0@Wih1 + h1@Whh1)
// blocks 64..127: layer0 gates (t+1), cols [(bid-64)*64, +64), K=1024 (h0@Whh0)
// Every thread owns one (b,j) cell for layer0 AND layer1 (c,h in registers).
__global__ void __launch_bounds__(256)
persist_kernel(const float* __restrict__ bih1, const float* __restrict__ bhh1,
               const int* __restrict__ lengths)
{
    __shared__ __align__(16) float sm[8192];   // 32KB: staging (26KB) / partials (32KB)
    const int bid = blockIdx.x, tid = threadIdx.x;
    const int lane = tid & 31, warp = tid >> 5;
    const int isL1 = bid < 64;
    const int colbase = (isL1 ? bid : bid - 64) * 64;

    const int gtid = bid * 256 + tid;            // 0..32767
    const int b = gtid >> 10, j = gtid & 1023;
    const int len = lengths[b];
    const float bs0 = bih1[j]        + bhh1[j];
    const float bs1 = bih1[j + 1024] + bhh1[j + 1024];
    const float bs2 = bih1[j + 2048] + bhh1[j + 2048];
    const float bs3 = bih1[j + 3072] + bhh1[j + 3072];

    float c0r, h0r, c1r = 0.f, h1r = 0.f;
    g_hh1[gtid] = __float2half_rn(0.f);
    // prologue: cell0(t=0): h_prev = 0 -> gates = pre0[b,0]; mask always true (len>=1)
    {
        const float* pg = g_pre0 + (size_t)(b * TT) * G4 + j;
        float ig = sigmoidf_(pg[0]);
        float gg = tanhf(pg[2048]);
        float og = sigmoidf_(pg[3072]);
        c0r = ig * gg;
        h0r = og * tanhf(c0r);
        g_hh0[gtid] = __float2half_rn(h0r);
    }
    gridbar();

    for (int t = 0; t < TT; t++) {
        // ---- phase A: GEMMs ----
        if (isL1) {
            step_gemm_block(1, colbase, g_gates1, sm, lane, warp);
        } else if (t < TT - 1) {
            step_gemm_block(0, colbase, g_gates0, sm, lane, warp);
        }
        gridbar();

        // ---- phase B: cells ----
        {   // cell1(t)
            const float* gp = g_gates1 + b * G4 + j;
            float si = __ldcg(gp)        + bs0;
            float sf = __ldcg(gp + 1024) + bs1;
            float sg = __ldcg(gp + 2048) + bs2;
            float so = __ldcg(gp + 3072) + bs3;
            float ig = sigmoidf_(si), fg = sigmoidf_(sf);
            float gg = tanhf(sg),     og = sigmoidf_(so);
            float cn = fg * c1r + ig * gg;
            float hn = og * tanhf(cn);
            if (t < len) { c1r = cn; h1r = hn; }
            __half hv = __float2half_rn(h1r);
            g_hh1[gtid] = hv;
            g_outhh[(size_t)(b * TT + t) * HH + j] = hv;
        }
        if (t < TT - 1) {   // cell0(t+1)
            const float* gp = g_gates0 + b * G4 + j;
            const float* pp = g_pre0 + (size_t)(b * TT + t + 1) * G4 + j;
            float si = __ldcg(gp)        + pp[0];
            float sf = __ldcg(gp + 1024) + pp[1024];
            float sg = __ldcg(gp + 2048) + pp[2048];
            float so = __ldcg(gp + 3072) + pp[3072];
            float ig = sigmoidf_(si), fg = sigmoidf_(sf);
            float gg = tanhf(sg),     og = sigmoidf_(so);
            float cn = fg * c0r + ig * gg;
            float hn = og * tanhf(cn);
            if (t + 1 < len) { c0r = cn; h0r = hn; }
            g_hh0[gtid] = __float2half_rn(h0r);
        }
        gridbar();
    }
}

// ---------------- projection: logits = outh(fp16) @ Wout(fp16)^T + bout -------------
// M=6400, N=20000, K=1024. BM=BN=128, Kc=32, fully-masked row tiles skipped. (R9-proven)
__global__ void __launch_bounds__(256)
proj_gemm(const float* __restrict__ bout, const int* __restrict__ lengths,
          float* __restrict__ out)
{
    __shared__ __half As[128 * 40];
    __shared__ __half Bs[128 * 40];
    const int r0 = blockIdx.y * 128, c0 = blockIdx.x * 128;
    const int tid = threadIdx.x, lane = tid & 31, warp = tid >> 5;
    const int wm = warp >> 2, wn = warp & 3, lm = lane >> 2, lk = lane & 3;

    {
        int rr = r0 + (tid & 127);
        int act = ((rr % TT) < lengths[rr / TT]) ? 1 : 0;
        if (!__syncthreads_or(act)) return;
    }

    const int srow = tid >> 1, soff = (tid & 1) * 16;
    const __half* Asrc = g_outhh + (size_t)(r0 + srow) * HH;
    int nr = c0 + srow; if (nr > VV - 1) nr = VV - 1;
    const __half* Bsrc = hWout + (size_t)nr * HH;

    float acc[4][4][4];
    #pragma unroll
    for (int mt = 0; mt < 4; mt++)
        #pragma unroll
        for (int nt = 0; nt < 4; nt++)
            #pragma unroll
            for (int q = 0; q < 4; q++) acc[mt][nt][q] = 0.f;

    uint4 av0, av1, bv0, bv1;
    av0 = *(const uint4*)(Asrc + soff);     av1 = *(const uint4*)(Asrc + soff + 8);
    bv0 = *(const uint4*)(Bsrc + soff);     bv1 = *(const uint4*)(Bsrc + soff + 8);

    for (int c = 0; c < 32; c++) {
        __syncthreads();
        *(uint4*)&As[srow * 40 + soff]     = av0;
        *(uint4*)&As[srow * 40 + soff + 8] = av1;
        *(uint4*)&Bs[srow * 40 + soff]     = bv0;
        *(uint4*)&Bs[srow * 40 + soff + 8] = bv1;
        __syncthreads();
        if (c + 1 < 32) {
            int k0 = (c + 1) * 32;
            av0 = *(const uint4*)(Asrc + k0 + soff); av1 = *(const uint4*)(Asrc + k0 + soff + 8);
            bv0 = *(const uint4*)(Bsrc + k0 + soff); bv1 = *(const uint4*)(Bsrc + k0 + soff + 8);
        }
        #pragma unroll
        for (int it = 0; it < 2; it++) {
            const int kw = it * 16 + 2 * lk;
            unsigned a[4][4], b[4][2];
            #pragma unroll
            for (int mt = 0; mt < 4; mt++) {
                const __half* Ar = &As[(wm * 64 + mt * 16 + lm) * 40 + kw];
                a[mt][0] = *(const unsigned*)Ar;
                a[mt][1] = *(const unsigned*)(Ar + 8 * 40);
                a[mt][2] = *(const unsigned*)(Ar + 8);
                a[mt][3] = *(const unsigned*)(Ar + 8 * 40 + 8);
            }
            #pragma unroll
            for (int nt = 0; nt < 4; nt++) {
                const __half* Br = &Bs[(wn * 32 + nt * 8 + lm) * 40 + kw];
                b[nt][0] = *(const unsigned*)Br;
                b[nt][1] = *(const unsigned*)(Br + 8);
            }
            #pragma unroll
            for (int mt = 0; mt < 4; mt++)
                #pragma unroll
                for (int nt = 0; nt < 4; nt++)
                    mma16(acc[mt][nt], a[mt], b[nt]);
        }
    }

    bool rmask[8];
    #pragma unroll
    for (int mt = 0; mt < 4; mt++) {
        int gr0 = r0 + wm * 64 + mt * 16 + lm, gr1 = gr0 + 8;
        rmask[2 * mt]     = (gr0 % TT) < lengths[gr0 / TT];
        rmask[2 * mt + 1] = (gr1 % TT) < lengths[gr1 / TT];
    }
    #pragma unroll
    for (int nt = 0; nt < 4; nt++) {
        int cc = c0 + wn * 32 + nt * 8 + 2 * lk;
        bool v0 = cc < VV, v1 = (cc + 1) < VV;
        float b0 = v0 ? bout[cc] : 0.f, b1 = v1 ? bout[cc + 1] : 0.f;
        #pragma unroll
        for (int mt = 0; mt < 4; mt++) {
            int gr0 = r0 + wm * 64 + mt * 16 + lm, gr1 = gr0 + 8;
            if (rmask[2 * mt]) {
                if (v0) out[(size_t)gr0 * VV + cc]     = acc[mt][nt][0] + b0;
                if (v1) out[(size_t)gr0 * VV + cc + 1] = acc[mt][nt][1] + b1;
            }
            if (rmask[2 * mt + 1]) {
                if (v0) out[(size_t)gr1 * VV + cc]     = acc[mt][nt][2] + b0;
                if (v1) out[(size_t)gr1 * VV + cc + 1] = acc[mt][nt][3] + b1;
            }
        }
    }
}

// ---------------- fill masked rows: logits[b, t>=len] = logits[b, len-1] ----------------
__global__ void copyfill(const int* __restrict__ lengths, float* __restrict__ out)
{
    int t = blockIdx.x, b = blockIdx.y;
    int L = lengths[b];
    if (t < L) return;
    const float4* src = (const float4*)(out + ((size_t)b * TT + (L - 1)) * VV);
    float4* dst = (float4*)(out + ((size_t)b * TT + t) * VV);
    for (int i = threadIdx.x; i < VV / 4; i += blockDim.x) dst[i] = src[i];
}

// ---------------- launch ----------------
extern "C" void kernel_launch(void* const* d_in, const int* in_sizes, int n_in,
                              void* d_out, int out_size)
{
    const int*   ids     = (const int*)d_in[0];
    const int*   lengths = (const int*)d_in[1];
    const float* emb     = (const float*)d_in[2];
    const float* Wih0    = (const float*)d_in[3];
    const float* Whh0    = (const float*)d_in[4];
    const float* bih0    = (const float*)d_in[5];
    const float* bhh0    = (const float*)d_in[6];
    const float* Wih1    = (const float*)d_in[7];
    const float* Whh1    = (const float*)d_in[8];
    const float* bih1    = (const float*)d_in[9];
    const float* bhh1    = (const float*)d_in[10];
    const float* Wout    = (const float*)d_in[11];
    const float* bout    = (const float*)d_in[12];
    float* out = (float*)d_out;

    // 0) fp16 weight conversion + bias combine
    __half *w0, *w1, *w2, *w3, *wo;
    cudaGetSymbolAddress((void**)&w0, hWhh0);
    cudaGetSymbolAddress((void**)&w1, hWih1);
    cudaGetSymbolAddress((void**)&w2, hWhh1);
    cudaGetSymbolAddress((void**)&w3, hWih0);
    cudaGetSymbolAddress((void**)&wo, hWout);
    conv_h16<<<4096, 256>>>(w0, Whh0);          // 4096*1024
    conv_h16<<<4096, 256>>>(w1, Wih1);
    conv_h16<<<4096, 256>>>(w2, Whh1);
    conv_h16<<<1024, 256>>>(w3, Wih0);          // 4096*256
    conv_h16<<<20000, 256>>>(wo, Wout);         // 20000*1024
    conv_b0<<<16, 256>>>(bih0, bhh0);

    // 1) precompute layer0 input gates (+biases): M=6400, N=4096, K=256 (fp16 mma)
    pre_gemm<<<dim3(G4 / 128, RR / 128), 256>>>(ids, emb, lengths);

    // 2) full recurrence in one persistent kernel (two-phase, fp16 mma)
    persist_kernel<<<NBLK, 256>>>(bih1, bhh1, lengths);

    // 3) projection (fp16 operands, fp32 accumulate/output)
    proj_gemm<<<dim3((VV + 127) / 128, RR / 128), 256>>>(bout, lengths, out);

    // 4) duplicate frozen rows
    copyfill<<<dim3(TT, BB), 256>>>(lengths, out);
}